// round 2
// baseline (speedup 1.0000x reference)
#include <cuda_runtime.h>
#include <math.h>

#define C_DIM 512
#define N_DIM 64
#define HW_DIM 1024
#define M_TOT (N_DIM * HW_DIM)   // 65536
#define EPS_V 1e-5f
#define T_ITERS 5

// ---------------- scratch (no allocation allowed) ----------------
__device__ float g_mean[C_DIM];
__device__ float g_bias[C_DIM];
__device__ float g_Gram[C_DIM * C_DIM];
__device__ float g_S[C_DIM * C_DIM];       // Sigma, then Sigma_N (in place scale)
__device__ float g_Pa[C_DIM * C_DIM];
__device__ float g_Pb[C_DIM * C_DIM];
__device__ float g_P2[C_DIM * C_DIM];
__device__ float g_P3[C_DIM * C_DIM];
__device__ float g_trace;
__device__ float g_rTr;

// ---------------- mean per channel + zero scratch ----------------
__global__ void mean_kernel(const float* __restrict__ X) {
    int c = blockIdx.x;
    float s = 0.f;
    // 16384 float4 per channel
    for (int idx = threadIdx.x; idx < (M_TOT / 4); idx += 256) {
        int n = idx >> 8;            // 256 float4 per (n, c) row of 1024
        int h4 = idx & 255;
        const float4 v = *(const float4*)&X[(((size_t)(n * C_DIM + c)) << 10) + (size_t)h4 * 4];
        s += (v.x + v.y) + (v.z + v.w);
    }
    __shared__ float red[256];
    red[threadIdx.x] = s;
    __syncthreads();
    for (int off = 128; off > 0; off >>= 1) {
        if (threadIdx.x < off) red[threadIdx.x] += red[threadIdx.x + off];
        __syncthreads();
    }
    if (threadIdx.x == 0) g_mean[c] = red[0] * (1.0f / (float)M_TOT);
    // zero Gram row c (must happen every graph replay, before gram_kernel)
    for (int j = threadIdx.x; j < C_DIM; j += 256) g_Gram[c * C_DIM + j] = 0.f;
    if (c == 0 && threadIdx.x == 0) g_trace = 0.f;
}

// ---------------- Gram = x x^T (upper tiles only), split over n ----------------
// grid (36, 16), block 256. blockIdx.x -> (bi,bj) with bi<=bj ; blockIdx.y -> 4 n's
__global__ void gram_kernel(const float* __restrict__ X) {
    int t = blockIdx.x;
    int bi = 0;
    while (t >= 8 - bi) { t -= 8 - bi; bi++; }
    int bj = bi + t;

    __shared__ float As[32][68];
    __shared__ float Bs[32][68];

    const int tid = threadIdx.x;
    const int tx = tid & 15, ty = tid >> 4;
    float acc[4][4] = {};

    const int n0 = blockIdx.y * (N_DIM / 16);
    for (int n = n0; n < n0 + (N_DIM / 16); n++) {
        const float* A = X + (((size_t)(n * C_DIM + bi * 64)) << 10);
        const float* B = X + (((size_t)(n * C_DIM + bj * 64)) << 10);
        for (int k0 = 0; k0 < HW_DIM; k0 += 32) {
#pragma unroll
            for (int r = 0; r < 2; r++) {
                int lid = tid + r * 256;          // 0..511
                int k4 = lid & 7, row = lid >> 3; // row 0..63
                float4 v = *(const float4*)&A[(size_t)row * HW_DIM + k0 + k4 * 4];
                As[k4 * 4 + 0][row] = v.x; As[k4 * 4 + 1][row] = v.y;
                As[k4 * 4 + 2][row] = v.z; As[k4 * 4 + 3][row] = v.w;
                float4 u = *(const float4*)&B[(size_t)row * HW_DIM + k0 + k4 * 4];
                Bs[k4 * 4 + 0][row] = u.x; Bs[k4 * 4 + 1][row] = u.y;
                Bs[k4 * 4 + 2][row] = u.z; Bs[k4 * 4 + 3][row] = u.w;
            }
            __syncthreads();
#pragma unroll
            for (int kk = 0; kk < 32; kk++) {
                float4 a = *(const float4*)&As[kk][ty * 4];
                float4 b = *(const float4*)&Bs[kk][tx * 4];
                float av[4] = {a.x, a.y, a.z, a.w};
                float bv[4] = {b.x, b.y, b.z, b.w};
#pragma unroll
                for (int i = 0; i < 4; i++)
#pragma unroll
                    for (int j = 0; j < 4; j++)
                        acc[i][j] = fmaf(av[i], bv[j], acc[i][j]);
            }
            __syncthreads();
        }
    }
    const int ibase = bi * 64 + ty * 4;
    const int jbase = bj * 64 + tx * 4;
#pragma unroll
    for (int i = 0; i < 4; i++)
#pragma unroll
        for (int j = 0; j < 4; j++)
            atomicAdd(&g_Gram[(ibase + i) * C_DIM + jbase + j], acc[i][j]);
}

// ---------------- Sigma = Gram/m - mu mu^T + eps I ; trace ; P = I ----------------
__global__ void finalize_sigma() {
    int i = blockIdx.x;
    float mi = g_mean[i];
    for (int j = threadIdx.x; j < C_DIM; j += 256) {
        float raw = ((i >> 6) <= (j >> 6)) ? g_Gram[i * C_DIM + j] : g_Gram[j * C_DIM + i];
        float s = raw * (1.0f / (float)M_TOT) - mi * g_mean[j];
        if (i == j) { s += EPS_V; atomicAdd(&g_trace, s); }
        g_S[i * C_DIM + j] = s;
        g_Pa[i * C_DIM + j] = (i == j) ? 1.f : 0.f;
    }
}

// ---------------- Sigma_N = Sigma / trace ----------------
__global__ void scale_sigma() {
    float r = 1.0f / g_trace;
    int idx = blockIdx.x * 256 + threadIdx.x;
    g_S[idx] *= r;
    if (idx == 0) g_rTr = r;
}

// ---------------- C = alpha*(A@B) + beta*D  (512x512x512) ----------------
// grid (8,8), block 256
__global__ void gemm512(float* __restrict__ Cm, const float* __restrict__ A,
                        const float* __restrict__ B, const float* __restrict__ D,
                        float alpha, float beta) {
    __shared__ float As[32][68];
    __shared__ float Bs[32][68];
    const int bi = blockIdx.y, bj = blockIdx.x;
    const int tid = threadIdx.x;
    const int tx = tid & 15, ty = tid >> 4;
    float acc[4][4] = {};

    for (int k0 = 0; k0 < C_DIM; k0 += 32) {
#pragma unroll
        for (int r = 0; r < 2; r++) {
            int lid = tid + r * 256;
            int k4 = lid & 7, row = lid >> 3;
            float4 v = *(const float4*)&A[(size_t)(bi * 64 + row) * C_DIM + k0 + k4 * 4];
            As[k4 * 4 + 0][row] = v.x; As[k4 * 4 + 1][row] = v.y;
            As[k4 * 4 + 2][row] = v.z; As[k4 * 4 + 3][row] = v.w;
        }
#pragma unroll
        for (int r = 0; r < 2; r++) {
            int lid = tid + r * 256;
            int j4 = lid & 15, kk = (lid >> 4); // kk 0..31
            float4 v = *(const float4*)&B[(size_t)(k0 + kk) * C_DIM + bj * 64 + j4 * 4];
            *(float4*)&Bs[kk][j4 * 4] = v;
        }
        __syncthreads();
#pragma unroll
        for (int kk = 0; kk < 32; kk++) {
            float4 a = *(const float4*)&As[kk][ty * 4];
            float4 b = *(const float4*)&Bs[kk][tx * 4];
            float av[4] = {a.x, a.y, a.z, a.w};
            float bv[4] = {b.x, b.y, b.z, b.w};
#pragma unroll
            for (int i = 0; i < 4; i++)
#pragma unroll
                for (int j = 0; j < 4; j++)
                    acc[i][j] = fmaf(av[i], bv[j], acc[i][j]);
        }
        __syncthreads();
    }
#pragma unroll
    for (int i = 0; i < 4; i++)
#pragma unroll
        for (int j = 0; j < 4; j++) {
            size_t idx = (size_t)(bi * 64 + ty * 4 + i) * C_DIM + bj * 64 + tx * 4 + j;
            float v = alpha * acc[i][j];
            if (D) v = fmaf(beta, D[idx], v);
            Cm[idx] = v;
        }
}

// ---------------- bias[c] = sqrt(rTr) * dot(P[c,:], mean) ----------------
__global__ void bias_kernel(const float* __restrict__ P) {
    int c = blockIdx.x * 256 + threadIdx.x;
    float s = 0.f;
    for (int j = 0; j < C_DIM; j++) s = fmaf(P[c * C_DIM + j], g_mean[j], s);
    g_bias[c] = sqrtf(g_rTr) * s;
}

// ---------------- Out[n] = sqrt(rTr)*(P @ X_n) - bias ----------------
// grid (16, 8, 64), block 256
__global__ void out_kernel(const float* __restrict__ X, const float* __restrict__ P,
                           float* __restrict__ Out) {
    __shared__ float As[32][68];
    __shared__ float Bs[32][68];
    const int n = blockIdx.z, bs = blockIdx.x, bc = blockIdx.y;
    const int tid = threadIdx.x;
    const int tx = tid & 15, ty = tid >> 4;
    float acc[4][4] = {};
    const float* B = X + (((size_t)n * C_DIM) << 10);

    for (int k0 = 0; k0 < C_DIM; k0 += 32) {
#pragma unroll
        for (int r = 0; r < 2; r++) {
            int lid = tid + r * 256;
            int k4 = lid & 7, row = lid >> 3;
            float4 v = *(const float4*)&P[(size_t)(bc * 64 + row) * C_DIM + k0 + k4 * 4];
            As[k4 * 4 + 0][row] = v.x; As[k4 * 4 + 1][row] = v.y;
            As[k4 * 4 + 2][row] = v.z; As[k4 * 4 + 3][row] = v.w;
        }
#pragma unroll
        for (int r = 0; r < 2; r++) {
            int lid = tid + r * 256;
            int j4 = lid & 15, kk = lid >> 4;
            float4 v = *(const float4*)&B[(size_t)(k0 + kk) * HW_DIM + bs * 64 + j4 * 4];
            *(float4*)&Bs[kk][j4 * 4] = v;
        }
        __syncthreads();
#pragma unroll
        for (int kk = 0; kk < 32; kk++) {
            float4 a = *(const float4*)&As[kk][ty * 4];
            float4 b = *(const float4*)&Bs[kk][tx * 4];
            float av[4] = {a.x, a.y, a.z, a.w};
            float bv[4] = {b.x, b.y, b.z, b.w};
#pragma unroll
            for (int i = 0; i < 4; i++)
#pragma unroll
                for (int j = 0; j < 4; j++)
                    acc[i][j] = fmaf(av[i], bv[j], acc[i][j]);
        }
        __syncthreads();
    }
    const float sc = sqrtf(g_rTr);
#pragma unroll
    for (int i = 0; i < 4; i++) {
        int c = bc * 64 + ty * 4 + i;
        float bv = g_bias[c];
#pragma unroll
        for (int j = 0; j < 4; j++) {
            size_t idx = (((size_t)(n * C_DIM + c)) << 10) + bs * 64 + tx * 4 + j;
            Out[idx] = sc * acc[i][j] - bv;
        }
    }
}

// ---------------- launch ----------------
extern "C" void kernel_launch(void* const* d_in, const int* in_sizes, int n_in,
                              void* d_out, int out_size) {
    const float* X = (const float*)d_in[0];
    float* Out = (float*)d_out;

    float *Pa, *Pb, *P2, *P3, *S;
    cudaGetSymbolAddress((void**)&Pa, g_Pa);
    cudaGetSymbolAddress((void**)&Pb, g_Pb);
    cudaGetSymbolAddress((void**)&P2, g_P2);
    cudaGetSymbolAddress((void**)&P3, g_P3);
    cudaGetSymbolAddress((void**)&S,  g_S);

    mean_kernel<<<C_DIM, 256>>>(X);
    gram_kernel<<<dim3(36, 16), 256>>>(X);
    finalize_sigma<<<C_DIM, 256>>>();
    scale_sigma<<<(C_DIM * C_DIM) / 256, 256>>>();

    float* cur = Pa;
    float* nxt = Pb;
    for (int it = 0; it < T_ITERS; it++) {
        gemm512<<<dim3(8, 8), 256>>>(P2, cur, cur, (const float*)nullptr, 1.f, 0.f);
        gemm512<<<dim3(8, 8), 256>>>(P3, P2, cur, (const float*)nullptr, 1.f, 0.f);
        gemm512<<<dim3(8, 8), 256>>>(nxt, P3, S, cur, -0.5f, 1.5f);
        float* tmp = cur; cur = nxt; nxt = tmp;
    }

    bias_kernel<<<2, 256>>>(cur);
    out_kernel<<<dim3(16, 8, 64), 256>>>(X, cur, Out);
}

// round 3
// speedup vs baseline: 1.0026x; 1.0026x over previous
#include <cuda_runtime.h>
#include <math.h>

#define C_DIM 512
#define N_DIM 64
#define HW_DIM 1024
#define M_TOT (N_DIM * HW_DIM)   // 65536
#define EPS_V 1e-5f
#define T_ITERS 5

// ---------------- scratch (no allocation allowed) ----------------
__device__ float g_mean[C_DIM];
__device__ float g_bias[C_DIM];
__device__ float g_Gram[C_DIM * C_DIM];
__device__ float g_S[C_DIM * C_DIM];       // Sigma, then Sigma_N (in place scale)
__device__ float g_Pa[C_DIM * C_DIM];
__device__ float g_Pb[C_DIM * C_DIM];
__device__ float g_P2[C_DIM * C_DIM];
__device__ float g_P3[C_DIM * C_DIM];
__device__ float g_trace;
__device__ float g_rTr;

// ---------------- mean per channel + zero scratch ----------------
__global__ void mean_kernel(const float* __restrict__ X) {
    int c = blockIdx.x;
    float s = 0.f;
    // 16384 float4 per channel
    for (int idx = threadIdx.x; idx < (M_TOT / 4); idx += 256) {
        int n = idx >> 8;            // 256 float4 per (n, c) row of 1024
        int h4 = idx & 255;
        const float4 v = *(const float4*)&X[(((size_t)(n * C_DIM + c)) << 10) + (size_t)h4 * 4];
        s += (v.x + v.y) + (v.z + v.w);
    }
    __shared__ float red[256];
    red[threadIdx.x] = s;
    __syncthreads();
    for (int off = 128; off > 0; off >>= 1) {
        if (threadIdx.x < off) red[threadIdx.x] += red[threadIdx.x + off];
        __syncthreads();
    }
    if (threadIdx.x == 0) g_mean[c] = red[0] * (1.0f / (float)M_TOT);
    // zero Gram row c (must happen every graph replay, before gram_kernel)
    for (int j = threadIdx.x; j < C_DIM; j += 256) g_Gram[c * C_DIM + j] = 0.f;
    if (c == 0 && threadIdx.x == 0) g_trace = 0.f;
}

// ---------------- Gram = x x^T (upper tiles only), split over n ----------------
// grid (36, 16), block 256. blockIdx.x -> (bi,bj) with bi<=bj ; blockIdx.y -> 4 n's
__global__ void gram_kernel(const float* __restrict__ X) {
    int t = blockIdx.x;
    int bi = 0;
    while (t >= 8 - bi) { t -= 8 - bi; bi++; }
    int bj = bi + t;

    __shared__ float As[32][68];
    __shared__ float Bs[32][68];

    const int tid = threadIdx.x;
    const int tx = tid & 15, ty = tid >> 4;
    float acc[4][4] = {};

    const int n0 = blockIdx.y * (N_DIM / 16);
    for (int n = n0; n < n0 + (N_DIM / 16); n++) {
        const float* A = X + (((size_t)(n * C_DIM + bi * 64)) << 10);
        const float* B = X + (((size_t)(n * C_DIM + bj * 64)) << 10);
        for (int k0 = 0; k0 < HW_DIM; k0 += 32) {
#pragma unroll
            for (int r = 0; r < 2; r++) {
                int lid = tid + r * 256;          // 0..511
                int k4 = lid & 7, row = lid >> 3; // row 0..63
                float4 v = *(const float4*)&A[(size_t)row * HW_DIM + k0 + k4 * 4];
                As[k4 * 4 + 0][row] = v.x; As[k4 * 4 + 1][row] = v.y;
                As[k4 * 4 + 2][row] = v.z; As[k4 * 4 + 3][row] = v.w;
                float4 u = *(const float4*)&B[(size_t)row * HW_DIM + k0 + k4 * 4];
                Bs[k4 * 4 + 0][row] = u.x; Bs[k4 * 4 + 1][row] = u.y;
                Bs[k4 * 4 + 2][row] = u.z; Bs[k4 * 4 + 3][row] = u.w;
            }
            __syncthreads();
#pragma unroll
            for (int kk = 0; kk < 32; kk++) {
                float4 a = *(const float4*)&As[kk][ty * 4];
                float4 b = *(const float4*)&Bs[kk][tx * 4];
                float av[4] = {a.x, a.y, a.z, a.w};
                float bv[4] = {b.x, b.y, b.z, b.w};
#pragma unroll
                for (int i = 0; i < 4; i++)
#pragma unroll
                    for (int j = 0; j < 4; j++)
                        acc[i][j] = fmaf(av[i], bv[j], acc[i][j]);
            }
            __syncthreads();
        }
    }
    const int ibase = bi * 64 + ty * 4;
    const int jbase = bj * 64 + tx * 4;
#pragma unroll
    for (int i = 0; i < 4; i++)
#pragma unroll
        for (int j = 0; j < 4; j++)
            atomicAdd(&g_Gram[(ibase + i) * C_DIM + jbase + j], acc[i][j]);
}

// ---------------- Sigma = Gram/m - mu mu^T + eps I ; trace ; P = I ----------------
__global__ void finalize_sigma() {
    int i = blockIdx.x;
    float mi = g_mean[i];
    for (int j = threadIdx.x; j < C_DIM; j += 256) {
        float raw = ((i >> 6) <= (j >> 6)) ? g_Gram[i * C_DIM + j] : g_Gram[j * C_DIM + i];
        float s = raw * (1.0f / (float)M_TOT) - mi * g_mean[j];
        if (i == j) { s += EPS_V; atomicAdd(&g_trace, s); }
        g_S[i * C_DIM + j] = s;
        g_Pa[i * C_DIM + j] = (i == j) ? 1.f : 0.f;
    }
}

// ---------------- Sigma_N = Sigma / trace ----------------
__global__ void scale_sigma() {
    float r = 1.0f / g_trace;
    int idx = blockIdx.x * 256 + threadIdx.x;
    g_S[idx] *= r;
    if (idx == 0) g_rTr = r;
}

// ---------------- C = alpha*(A@B) + beta*D  (512x512x512) ----------------
// grid (8,8), block 256
__global__ void gemm512(float* __restrict__ Cm, const float* __restrict__ A,
                        const float* __restrict__ B, const float* __restrict__ D,
                        float alpha, float beta) {
    __shared__ float As[32][68];
    __shared__ float Bs[32][68];
    const int bi = blockIdx.y, bj = blockIdx.x;
    const int tid = threadIdx.x;
    const int tx = tid & 15, ty = tid >> 4;
    float acc[4][4] = {};

    for (int k0 = 0; k0 < C_DIM; k0 += 32) {
#pragma unroll
        for (int r = 0; r < 2; r++) {
            int lid = tid + r * 256;
            int k4 = lid & 7, row = lid >> 3;
            float4 v = *(const float4*)&A[(size_t)(bi * 64 + row) * C_DIM + k0 + k4 * 4];
            As[k4 * 4 + 0][row] = v.x; As[k4 * 4 + 1][row] = v.y;
            As[k4 * 4 + 2][row] = v.z; As[k4 * 4 + 3][row] = v.w;
        }
#pragma unroll
        for (int r = 0; r < 2; r++) {
            int lid = tid + r * 256;
            int j4 = lid & 15, kk = (lid >> 4); // kk 0..31
            float4 v = *(const float4*)&B[(size_t)(k0 + kk) * C_DIM + bj * 64 + j4 * 4];
            *(float4*)&Bs[kk][j4 * 4] = v;
        }
        __syncthreads();
#pragma unroll
        for (int kk = 0; kk < 32; kk++) {
            float4 a = *(const float4*)&As[kk][ty * 4];
            float4 b = *(const float4*)&Bs[kk][tx * 4];
            float av[4] = {a.x, a.y, a.z, a.w};
            float bv[4] = {b.x, b.y, b.z, b.w};
#pragma unroll
            for (int i = 0; i < 4; i++)
#pragma unroll
                for (int j = 0; j < 4; j++)
                    acc[i][j] = fmaf(av[i], bv[j], acc[i][j]);
        }
        __syncthreads();
    }
#pragma unroll
    for (int i = 0; i < 4; i++)
#pragma unroll
        for (int j = 0; j < 4; j++) {
            size_t idx = (size_t)(bi * 64 + ty * 4 + i) * C_DIM + bj * 64 + tx * 4 + j;
            float v = alpha * acc[i][j];
            if (D) v = fmaf(beta, D[idx], v);
            Cm[idx] = v;
        }
}

// ---------------- bias[c] = sqrt(rTr) * dot(P[c,:], mean) ----------------
__global__ void bias_kernel(const float* __restrict__ P) {
    int c = blockIdx.x * 256 + threadIdx.x;
    float s = 0.f;
    for (int j = 0; j < C_DIM; j++) s = fmaf(P[c * C_DIM + j], g_mean[j], s);
    g_bias[c] = sqrtf(g_rTr) * s;
}

// ---------------- Out[n] = sqrt(rTr)*(P @ X_n) - bias ----------------
// grid (16, 8, 64), block 256
__global__ void out_kernel(const float* __restrict__ X, const float* __restrict__ P,
                           float* __restrict__ Out) {
    __shared__ float As[32][68];
    __shared__ float Bs[32][68];
    const int n = blockIdx.z, bs = blockIdx.x, bc = blockIdx.y;
    const int tid = threadIdx.x;
    const int tx = tid & 15, ty = tid >> 4;
    float acc[4][4] = {};
    const float* B = X + (((size_t)n * C_DIM) << 10);

    for (int k0 = 0; k0 < C_DIM; k0 += 32) {
#pragma unroll
        for (int r = 0; r < 2; r++) {
            int lid = tid + r * 256;
            int k4 = lid & 7, row = lid >> 3;
            float4 v = *(const float4*)&P[(size_t)(bc * 64 + row) * C_DIM + k0 + k4 * 4];
            As[k4 * 4 + 0][row] = v.x; As[k4 * 4 + 1][row] = v.y;
            As[k4 * 4 + 2][row] = v.z; As[k4 * 4 + 3][row] = v.w;
        }
#pragma unroll
        for (int r = 0; r < 2; r++) {
            int lid = tid + r * 256;
            int j4 = lid & 15, kk = lid >> 4;
            float4 v = *(const float4*)&B[(size_t)(k0 + kk) * HW_DIM + bs * 64 + j4 * 4];
            *(float4*)&Bs[kk][j4 * 4] = v;
        }
        __syncthreads();
#pragma unroll
        for (int kk = 0; kk < 32; kk++) {
            float4 a = *(const float4*)&As[kk][ty * 4];
            float4 b = *(const float4*)&Bs[kk][tx * 4];
            float av[4] = {a.x, a.y, a.z, a.w};
            float bv[4] = {b.x, b.y, b.z, b.w};
#pragma unroll
            for (int i = 0; i < 4; i++)
#pragma unroll
                for (int j = 0; j < 4; j++)
                    acc[i][j] = fmaf(av[i], bv[j], acc[i][j]);
        }
        __syncthreads();
    }
    const float sc = sqrtf(g_rTr);
#pragma unroll
    for (int i = 0; i < 4; i++) {
        int c = bc * 64 + ty * 4 + i;
        float bv = g_bias[c];
#pragma unroll
        for (int j = 0; j < 4; j++) {
            size_t idx = (((size_t)(n * C_DIM + c)) << 10) + bs * 64 + tx * 4 + j;
            Out[idx] = sc * acc[i][j] - bv;
        }
    }
}

// ---------------- launch ----------------
extern "C" void kernel_launch(void* const* d_in, const int* in_sizes, int n_in,
                              void* d_out, int out_size) {
    const float* X = (const float*)d_in[0];
    float* Out = (float*)d_out;

    float *Pa, *Pb, *P2, *P3, *S;
    cudaGetSymbolAddress((void**)&Pa, g_Pa);
    cudaGetSymbolAddress((void**)&Pb, g_Pb);
    cudaGetSymbolAddress((void**)&P2, g_P2);
    cudaGetSymbolAddress((void**)&P3, g_P3);
    cudaGetSymbolAddress((void**)&S,  g_S);

    mean_kernel<<<C_DIM, 256>>>(X);
    gram_kernel<<<dim3(36, 16), 256>>>(X);
    finalize_sigma<<<C_DIM, 256>>>();
    scale_sigma<<<(C_DIM * C_DIM) / 256, 256>>>();

    float* cur = Pa;
    float* nxt = Pb;
    for (int it = 0; it < T_ITERS; it++) {
        gemm512<<<dim3(8, 8), 256>>>(P2, cur, cur, (const float*)nullptr, 1.f, 0.f);
        gemm512<<<dim3(8, 8), 256>>>(P3, P2, cur, (const float*)nullptr, 1.f, 0.f);
        gemm512<<<dim3(8, 8), 256>>>(nxt, P3, S, cur, -0.5f, 1.5f);
        float* tmp = cur; cur = nxt; nxt = tmp;
    }

    bias_kernel<<<2, 256>>>(cur);
    out_kernel<<<dim3(16, 8, 64), 256>>>(X, cur, Out);
}

// round 5
// speedup vs baseline: 1.9759x; 1.9708x over previous
#include <cuda_runtime.h>
#include <cuda_bf16.h>
#include <stdint.h>
#include <math.h>

typedef __nv_bfloat16 bf16;
typedef unsigned int u32;

#define C_DIM 512
#define M_TOT 65536
#define EPS_V 1e-5f

// GEMM tiling
#define BK 32
#define ROWB 80                  // padded smem row: 40 bf16 = 80 B (conflict-free ldmatrix)
#define TILE_B (128 * ROWB)      // 10240 B per operand tile
#define STAGE_B (4 * TILE_B)     // Ah, Al, Bh, Bl
#define GSMEM (2 * STAGE_B)      // 81920 B double-buffered

// ---------------- scratch (__device__ globals; no runtime allocation) ----------------
__device__ float g_mean[C_DIM];
__device__ float g_Gram[C_DIM * C_DIM];
__device__ float g_rTr;
__device__ bf16 g_Xh[33554432];   // centered X, [c][m] row-major
__device__ bf16 g_Xl[33554432];
__device__ bf16 g_Xth[33554432];  // centered X, [m][c] row-major
__device__ bf16 g_Xtl[33554432];
__device__ bf16 g_Sh[C_DIM * C_DIM], g_Sl[C_DIM * C_DIM];
__device__ bf16 g_PAh[C_DIM * C_DIM], g_PAl[C_DIM * C_DIM];
__device__ bf16 g_PBh[C_DIM * C_DIM], g_PBl[C_DIM * C_DIM];
__device__ bf16 g_T1h[C_DIM * C_DIM], g_T1l[C_DIM * C_DIM];
__device__ bf16 g_T2h[C_DIM * C_DIM], g_T2l[C_DIM * C_DIM];
__device__ bf16 g_Wh[C_DIM * C_DIM], g_Wl[C_DIM * C_DIM];
__device__ float g_PfA[C_DIM * C_DIM], g_PfB[C_DIM * C_DIM];
__device__ float g_AccA[C_DIM * C_DIM], g_AccB[C_DIM * C_DIM];

// ---------------- helpers ----------------
__device__ __forceinline__ u32 s2u(const void* p) {
    u32 a;
    asm("{ .reg .u64 t; cvta.to.shared.u64 t, %1; cvt.u32.u64 %0, t; }" : "=r"(a) : "l"(p));
    return a;
}
__device__ __forceinline__ void cpasync16(u32 dst, const void* src) {
    asm volatile("cp.async.cg.shared.global [%0], [%1], 16;" :: "r"(dst), "l"(src));
}
__device__ __forceinline__ void ldm4(u32* r, u32 addr) {
    asm volatile("ldmatrix.sync.aligned.m8n8.x4.shared.b16 {%0,%1,%2,%3}, [%4];"
                 : "=r"(r[0]), "=r"(r[1]), "=r"(r[2]), "=r"(r[3]) : "r"(addr));
}
__device__ __forceinline__ void mma16816(float* c, const u32* a, u32 b0, u32 b1) {
    asm volatile("mma.sync.aligned.m16n8k16.row.col.f32.bf16.bf16.f32 "
                 "{%0,%1,%2,%3}, {%4,%5,%6,%7}, {%8,%9}, {%0,%1,%2,%3};"
                 : "+f"(c[0]), "+f"(c[1]), "+f"(c[2]), "+f"(c[3])
                 : "r"(a[0]), "r"(a[1]), "r"(a[2]), "r"(a[3]), "r"(b0), "r"(b1));
}
__device__ __forceinline__ u32 splitpack(float a, float b, u32& lop) {
    bf16 h0 = __float2bfloat16(a), h1 = __float2bfloat16(b);
    bf16 l0 = __float2bfloat16(a - __bfloat162float(h0));
    bf16 l1 = __float2bfloat16(b - __bfloat162float(h1));
    __nv_bfloat162 hv, lv;
    hv.x = h0; hv.y = h1; lv.x = l0; lv.y = l1;
    lop = *(u32*)&lv;
    return *(u32*)&hv;
}

// ---------------- mean per channel + zero Gram ----------------
__global__ void mean_kernel(const float* __restrict__ X) {
    int c = blockIdx.x;
    float s = 0.f;
    for (int idx = threadIdx.x; idx < (M_TOT / 4); idx += 256) {
        int n = idx >> 8, h4 = idx & 255;
        const float4 v = *(const float4*)&X[(((size_t)(n * C_DIM + c)) << 10) + (size_t)h4 * 4];
        s += (v.x + v.y) + (v.z + v.w);
    }
    __shared__ float red[256];
    red[threadIdx.x] = s;
    __syncthreads();
    for (int off = 128; off > 0; off >>= 1) {
        if (threadIdx.x < off) red[threadIdx.x] += red[threadIdx.x + off];
        __syncthreads();
    }
    if (threadIdx.x == 0) g_mean[c] = red[0] * (1.0f / (float)M_TOT);
    for (int j = threadIdx.x; j < C_DIM; j += 256) g_Gram[(long)c * C_DIM + j] = 0.f;
}

// ---------------- center + split -> Xh/Xl [c][m] ----------------
__global__ void convA(const float* __restrict__ X) {
    int c = blockIdx.x;
    float mu = g_mean[c];
    u32* H = (u32*)&g_Xh[(long)c << 16];
    u32* L = (u32*)&g_Xl[(long)c << 16];
    for (int p = threadIdx.x; p < 32768; p += 256) {
        int m = p * 2, n = m >> 10, hw = m & 1023;
        const float2 v = *(const float2*)&X[(((long)(n * C_DIM + c)) << 10) + hw];
        u32 lo, hi = splitpack(v.x - mu, v.y - mu, lo);
        H[p] = hi; L[p] = lo;
    }
}

// ---------------- center + split + transpose -> Xth/Xtl [m][c] ----------------
__global__ void convB(const float* __restrict__ X) {
    __shared__ float smf[64][129];
    int b = blockIdx.x;                  // 0..511
    int n = b >> 3, hw0 = (b & 7) << 7;
    int tid = threadIdx.x;
    for (int cb = 0; cb < 8; cb++) {
        __syncthreads();
        for (int l = tid; l < 64 * 32; l += 256) {
            int cl = l >> 5, f4 = (l & 31) * 4;
            int ch = cb * 64 + cl;
            float4 v = *(const float4*)&X[(((long)(n * C_DIM + ch)) << 10) + hw0 + f4];
            float mu = g_mean[ch];
            smf[cl][f4] = v.x - mu; smf[cl][f4 + 1] = v.y - mu;
            smf[cl][f4 + 2] = v.z - mu; smf[cl][f4 + 3] = v.w - mu;
        }
        __syncthreads();
        for (int l = tid; l < 128 * 32; l += 256) {
            int r = l >> 5, j = l & 31;
            u32 lo, hi = splitpack(smf[2 * j][r], smf[2 * j + 1][r], lo);
            long m = (long)n * 1024 + hw0 + r;
            ((u32*)&g_Xth[m * C_DIM])[cb * 32 + j] = hi;
            ((u32*)&g_Xtl[m * C_DIM])[cb * 32 + j] = lo;
        }
    }
}

// ---------------- bf16x3 HMMA GEMM: C[128x128] += A @ B^T ----------------
// mode 0: atomicAdd into outF [512x512]
// mode 1: write NCHW output (rows = channels, cols = flattened m)
__global__ void __launch_bounds__(256, 1) gemm_hmma(
    const bf16* __restrict__ Ah, const bf16* __restrict__ Al, int lda,
    const bf16* __restrict__ Bh, const bf16* __restrict__ Bl, int ldb,
    int kSlice, int mode, float* __restrict__ outF)
{
    extern __shared__ char sm_raw[];
    u32 sbase = s2u(sm_raw);
    int tid = threadIdx.x, lane = tid & 31, wid = tid >> 5;
    int wm = wid >> 1, wn = wid & 1;                // warp tile 32 x 64
    int row0 = blockIdx.y * 128, col0 = blockIdx.x * 128;
    long k0 = (long)blockIdx.z * kSlice;
    int nSteps = kSlice / BK;

    float c[2][8][4];
#pragma unroll
    for (int mi = 0; mi < 2; mi++)
#pragma unroll
        for (int f = 0; f < 8; f++)
#pragma unroll
            for (int q = 0; q < 4; q++) c[mi][f][q] = 0.f;

    // ---- stage loader ----
    auto load_stage = [&](int st, int ks) {
        u32 sb = sbase + st * STAGE_B;
        long kg = k0 + (long)ks * BK;
#pragma unroll
        for (int t = 0; t < 4; t++) {
            const bf16* g = (t == 0) ? Ah : (t == 1) ? Al : (t == 2) ? Bh : Bl;
            int rbase = (t < 2) ? row0 : col0;
            int ld = (t < 2) ? lda : ldb;
#pragma unroll
            for (int rep = 0; rep < 2; rep++) {
                int idx = tid + rep * 256;
                int r = idx >> 2, ch = idx & 3;
                u32 dst = sb + t * TILE_B + r * ROWB + ch * 16;
                const void* src = g + (long)(rbase + r) * ld + kg + ch * 8;
                cpasync16(dst, src);
            }
        }
        asm volatile("cp.async.commit_group;");
    };

    load_stage(0, 0);
    for (int ks = 0; ks < nSteps; ks++) {
        if (ks + 1 < nSteps) {
            load_stage((ks + 1) & 1, ks + 1);
            asm volatile("cp.async.wait_group 1;" ::: "memory");
        } else {
            asm volatile("cp.async.wait_group 0;" ::: "memory");
        }
        __syncthreads();
        u32 sb = sbase + (ks & 1) * STAGE_B;
#pragma unroll
        for (int kk = 0; kk < 2; kk++) {
            int kcol = kk * 16;
            u32 ah[2][4], al[2][4], bh[4][4], bl[4][4];
#pragma unroll
            for (int mi = 0; mi < 2; mi++) {
                int r = wm * 32 + mi * 16 + (lane & 15);
                int cb = (kcol + (lane >> 4) * 8) * 2;
                ldm4(ah[mi], sb + 0 * TILE_B + r * ROWB + cb);
                ldm4(al[mi], sb + 1 * TILE_B + r * ROWB + cb);
            }
#pragma unroll
            for (int nj = 0; nj < 4; nj++) {
                int r = wn * 64 + nj * 16 + (lane & 7) + ((lane >> 4) << 3);
                int cb = (kcol + ((lane >> 3) & 1) * 8) * 2;
                ldm4(bh[nj], sb + 2 * TILE_B + r * ROWB + cb);
                ldm4(bl[nj], sb + 3 * TILE_B + r * ROWB + cb);
            }
#pragma unroll
            for (int mi = 0; mi < 2; mi++)
#pragma unroll
                for (int nj = 0; nj < 4; nj++) {
                    mma16816(c[mi][nj * 2],     ah[mi], bh[nj][0], bh[nj][1]);
                    mma16816(c[mi][nj * 2 + 1], ah[mi], bh[nj][2], bh[nj][3]);
                    mma16816(c[mi][nj * 2],     ah[mi], bl[nj][0], bl[nj][1]);
                    mma16816(c[mi][nj * 2 + 1], ah[mi], bl[nj][2], bl[nj][3]);
                    mma16816(c[mi][nj * 2],     al[mi], bh[nj][0], bh[nj][1]);
                    mma16816(c[mi][nj * 2 + 1], al[mi], bh[nj][2], bh[nj][3]);
                }
        }
        __syncthreads();
    }

    // ---- epilogue ----
    int rg = lane >> 2, cg = (lane & 3) * 2;
    if (mode == 0) {
#pragma unroll
        for (int mi = 0; mi < 2; mi++)
#pragma unroll
            for (int f = 0; f < 8; f++) {
                int rr = row0 + wm * 32 + mi * 16 + rg;
                int cc = col0 + wn * 64 + f * 8 + cg;
                atomicAdd(&outF[(long)rr * C_DIM + cc],           c[mi][f][0]);
                atomicAdd(&outF[(long)rr * C_DIM + cc + 1],       c[mi][f][1]);
                atomicAdd(&outF[(long)(rr + 8) * C_DIM + cc],     c[mi][f][2]);
                atomicAdd(&outF[(long)(rr + 8) * C_DIM + cc + 1], c[mi][f][3]);
            }
    } else {
        float* st = (float*)sm_raw;
        const int LDS = 132;
#pragma unroll
        for (int mi = 0; mi < 2; mi++)
#pragma unroll
            for (int f = 0; f < 8; f++) {
                int rr = wm * 32 + mi * 16 + rg;
                int cc = wn * 64 + f * 8 + cg;
                st[rr * LDS + cc] = c[mi][f][0];
                st[rr * LDS + cc + 1] = c[mi][f][1];
                st[(rr + 8) * LDS + cc] = c[mi][f][2];
                st[(rr + 8) * LDS + cc + 1] = c[mi][f][3];
            }
        __syncthreads();
        int n = col0 >> 10, hw0 = col0 & 1023;
        for (int l = tid; l < 128 * 32; l += 256) {
            int r = l >> 5, q = l & 31;
            float4 v = *(float4*)&st[r * LDS + q * 4];
            *(float4*)&outF[(((long)(n * C_DIM + row0 + r)) << 10) + hw0 + q * 4] = v;
        }
    }
}

// ---------------- trace -> rTr ----------------
__global__ void trace_k() {
    __shared__ float red[256];
    float s = 0.f;
    for (int i = threadIdx.x; i < C_DIM; i += 256) s += g_Gram[(long)i * (C_DIM + 1)];
    red[threadIdx.x] = s;
    __syncthreads();
    for (int off = 128; off > 0; off >>= 1) {
        if (threadIdx.x < off) red[threadIdx.x] += red[threadIdx.x + off];
        __syncthreads();
    }
    if (threadIdx.x == 0)
        g_rTr = 1.0f / (red[0] * (1.0f / (float)M_TOT) + (float)C_DIM * EPS_V);
}

// ---------------- Sigma_N split + P1 = 1.5I - 0.5 Sigma_N + zero AccA ----------------
__global__ void finalize_k() {
    int i = blockIdx.x;
    int j2 = threadIdx.x;     // pair index 0..255
    int j = j2 * 2;
    float rtr = g_rTr;
    float s0 = g_Gram[(long)i * C_DIM + j] * (1.f / (float)M_TOT);
    float s1 = g_Gram[(long)i * C_DIM + j + 1] * (1.f / (float)M_TOT);
    if (i == j) s0 += EPS_V;
    if (i == j + 1) s1 += EPS_V;
    s0 *= rtr; s1 *= rtr;
    u32 lo, hi = splitpack(s0, s1, lo);
    ((u32*)g_Sh)[i * 256 + j2] = hi; ((u32*)g_Sl)[i * 256 + j2] = lo;
    float p0 = ((i == j) ? 1.5f : 0.f) - 0.5f * s0;
    float p1 = ((i == j + 1) ? 1.5f : 0.f) - 0.5f * s1;
    g_PfA[(long)i * C_DIM + j] = p0;
    g_PfA[(long)i * C_DIM + j + 1] = p1;
    hi = splitpack(p0, p1, lo);
    ((u32*)g_PAh)[i * 256 + j2] = hi; ((u32*)g_PAl)[i * 256 + j2] = lo;
    g_AccA[(long)i * C_DIM + j] = 0.f;
    g_AccA[(long)i * C_DIM + j + 1] = 0.f;
}

// ---------------- f32 -> bf16 split, and zero another buffer ----------------
__global__ void split_k(const float* __restrict__ src, bf16* __restrict__ dh,
                        bf16* __restrict__ dl, float* __restrict__ zbuf) {
    int p = blockIdx.x * 256 + threadIdx.x;
    float a = src[p * 2], b = src[p * 2 + 1];
    u32 lo, hi = splitpack(a, b, lo);
    ((u32*)dh)[p] = hi; ((u32*)dl)[p] = lo;
    zbuf[p * 2] = 0.f; zbuf[p * 2 + 1] = 0.f;
}

// ---------------- NS combine: next = 1.5 P - 0.5 acc ; split (optionally * sqrt(rTr)) ----------------
__global__ void ns_combine(float* __restrict__ acc, const float* __restrict__ pc,
                           float* __restrict__ pn, bf16* __restrict__ dh,
                           bf16* __restrict__ dl, int scaleFlag) {
    int p = blockIdx.x * 256 + threadIdx.x;
    float sc = scaleFlag ? sqrtf(g_rTr) : 1.f;
    float v0 = fmaf(-0.5f, acc[p * 2], 1.5f * pc[p * 2]);
    float v1 = fmaf(-0.5f, acc[p * 2 + 1], 1.5f * pc[p * 2 + 1]);
    pn[p * 2] = v0; pn[p * 2 + 1] = v1;
    u32 lo, hi = splitpack(v0 * sc, v1 * sc, lo);
    ((u32*)dh)[p] = hi; ((u32*)dl)[p] = lo;
    acc[p * 2] = 0.f; acc[p * 2 + 1] = 0.f;
}

// ---------------- launch ----------------
extern "C" void kernel_launch(void* const* d_in, const int* in_sizes, int n_in,
                              void* d_out, int out_size) {
    const float* X = (const float*)d_in[0];
    float* Out = (float*)d_out;

    cudaFuncSetAttribute(gemm_hmma, cudaFuncAttributeMaxDynamicSharedMemorySize, GSMEM);

    void *xh, *xl, *xth, *xtl, *sh, *sl, *pah, *pal, *pbh, *pbl;
    void *t1h, *t1l, *t2h, *t2l, *wh, *wl, *pfa, *pfb, *acca, *accb, *gram;
    cudaGetSymbolAddress(&xh, g_Xh);   cudaGetSymbolAddress(&xl, g_Xl);
    cudaGetSymbolAddress(&xth, g_Xth); cudaGetSymbolAddress(&xtl, g_Xtl);
    cudaGetSymbolAddress(&sh, g_Sh);   cudaGetSymbolAddress(&sl, g_Sl);
    cudaGetSymbolAddress(&pah, g_PAh); cudaGetSymbolAddress(&pal, g_PAl);
    cudaGetSymbolAddress(&pbh, g_PBh); cudaGetSymbolAddress(&pbl, g_PBl);
    cudaGetSymbolAddress(&t1h, g_T1h); cudaGetSymbolAddress(&t1l, g_T1l);
    cudaGetSymbolAddress(&t2h, g_T2h); cudaGetSymbolAddress(&t2l, g_T2l);
    cudaGetSymbolAddress(&wh, g_Wh);   cudaGetSymbolAddress(&wl, g_Wl);
    cudaGetSymbolAddress(&pfa, g_PfA); cudaGetSymbolAddress(&pfb, g_PfB);
    cudaGetSymbolAddress(&acca, g_AccA); cudaGetSymbolAddress(&accb, g_AccB);
    cudaGetSymbolAddress(&gram, g_Gram);

    mean_kernel<<<C_DIM, 256>>>(X);
    convA<<<C_DIM, 256>>>(X);
    convB<<<512, 256>>>(X);

    // Gram = xc @ xc^T, K split 8 ways (128 CTAs = one wave), atomic f32 accumulate
    gemm_hmma<<<dim3(4, 4, 8), 256, GSMEM>>>(
        (const bf16*)xh, (const bf16*)xl, M_TOT,
        (const bf16*)xh, (const bf16*)xl, M_TOT, 8192, 0, (float*)gram);

    trace_k<<<1, 256>>>();
    finalize_k<<<C_DIM, 256>>>();

    // Newton-Schulz iterations 2..5 (iteration 1 folded into finalize_k)
    float *pfc = (float*)pfa, *pfn = (float*)pfb;
    bf16 *pch = (bf16*)pah, *pcl = (bf16*)pal, *pnh = (bf16*)pbh, *pnl = (bf16*)pbl;
    for (int it = 0; it < 4; it++) {
        int last = (it == 3);
        gemm_hmma<<<dim3(4, 4, 4), 256, GSMEM>>>(
            pch, pcl, C_DIM, pch, pcl, C_DIM, 128, 0, (float*)acca);
        split_k<<<512, 256>>>((const float*)acca, (bf16*)t1h, (bf16*)t1l, (float*)accb);
        gemm_hmma<<<dim3(4, 4, 4), 256, GSMEM>>>(
            (const bf16*)t1h, (const bf16*)t1l, C_DIM, pch, pcl, C_DIM, 128, 0, (float*)accb);
        split_k<<<512, 256>>>((const float*)accb, (bf16*)t2h, (bf16*)t2l, (float*)acca);
        gemm_hmma<<<dim3(4, 4, 4), 256, GSMEM>>>(
            (const bf16*)t2h, (const bf16*)t2l, C_DIM,
            (const bf16*)sh, (const bf16*)sl, C_DIM, 128, 0, (float*)acca);
        ns_combine<<<512, 256>>>((float*)acca, pfc, pfn,
                                 last ? (bf16*)wh : pnh, last ? (bf16*)wl : pnl, last);
        float* tf = pfc; pfc = pfn; pfn = tf;
        bf16* th = pch; pch = pnh; pnh = th;
        bf16* tl = pcl; pcl = pnl; pnl = tl;
    }

    // Out[c][m] = W @ xc, written NCHW
    gemm_hmma<<<dim3(512, 4, 1), 256, GSMEM>>>(
        (const bf16*)wh, (const bf16*)wl, C_DIM,
        (const bf16*)xth, (const bf16*)xtl, C_DIM, 512, 1, Out);
}

// round 6
// speedup vs baseline: 2.2192x; 1.1231x over previous
#include <cuda_runtime.h>
#include <cuda_bf16.h>
#include <stdint.h>
#include <math.h>

typedef __nv_bfloat16 bf16;
typedef unsigned int u32;

#define C_DIM 512
#define M_TOT 65536
#define EPS_V 1e-5f

// big GEMM tiling: CTA 128x128, BK=64, 8 warps (4x2), warp 32x64
#define ROWB 144                 // 64 bf16 = 128B data + 16B pad
#define TILE_B (128 * ROWB)      // 18432
#define STAGE_B (4 * TILE_B)     // 73728 (Ah, Al, Bh, Bl)
#define GSMEM (2 * STAGE_B)      // 147456

// small GEMM tiling: CTA 64x64, BK=64, 4 warps (2x2), warp 32x32
#define TILE64 (64 * ROWB)       // 9216
#define STAGE64 (4 * TILE64)     // 36864
#define GSMEM64 (2 * STAGE64)    // 73728

__constant__ int c_bi[10] = {0,0,0,0,1,1,1,2,2,3};
__constant__ int c_bj[10] = {0,1,2,3,1,2,3,2,3,3};

// ---------------- scratch ----------------
__device__ float g_mean[C_DIM];
__device__ float g_Gram[C_DIM * C_DIM];
__device__ float g_rTr;
__device__ bf16 g_Xh[33554432];   // centered X, [c][m]
__device__ bf16 g_Xl[33554432];
__device__ bf16 g_Xth[33554432];  // centered X, [m][c]
__device__ bf16 g_Xtl[33554432];
__device__ bf16 g_Sh[C_DIM * C_DIM], g_Sl[C_DIM * C_DIM];
__device__ bf16 g_PAh[C_DIM * C_DIM], g_PAl[C_DIM * C_DIM];
__device__ bf16 g_PBh[C_DIM * C_DIM], g_PBl[C_DIM * C_DIM];
__device__ bf16 g_T1h[C_DIM * C_DIM], g_T1l[C_DIM * C_DIM];
__device__ bf16 g_T2h[C_DIM * C_DIM], g_T2l[C_DIM * C_DIM];
__device__ bf16 g_Wh[C_DIM * C_DIM], g_Wl[C_DIM * C_DIM];
__device__ float g_PfA[C_DIM * C_DIM], g_PfB[C_DIM * C_DIM];

// ---------------- helpers ----------------
__device__ __forceinline__ u32 s2u(const void* p) {
    u32 a;
    asm("{ .reg .u64 t; cvta.to.shared.u64 t, %1; cvt.u32.u64 %0, t; }" : "=r"(a) : "l"(p));
    return a;
}
__device__ __forceinline__ void cpasync16(u32 dst, const void* src) {
    asm volatile("cp.async.cg.shared.global [%0], [%1], 16;" :: "r"(dst), "l"(src));
}
__device__ __forceinline__ void ldm4(u32* r, u32 addr) {
    asm volatile("ldmatrix.sync.aligned.m8n8.x4.shared.b16 {%0,%1,%2,%3}, [%4];"
                 : "=r"(r[0]), "=r"(r[1]), "=r"(r[2]), "=r"(r[3]) : "r"(addr));
}
__device__ __forceinline__ void mma16816(float* c, const u32* a, u32 b0, u32 b1) {
    asm volatile("mma.sync.aligned.m16n8k16.row.col.f32.bf16.bf16.f32 "
                 "{%0,%1,%2,%3}, {%4,%5,%6,%7}, {%8,%9}, {%0,%1,%2,%3};"
                 : "+f"(c[0]), "+f"(c[1]), "+f"(c[2]), "+f"(c[3])
                 : "r"(a[0]), "r"(a[1]), "r"(a[2]), "r"(a[3]), "r"(b0), "r"(b1));
}
__device__ __forceinline__ u32 splitpack(float a, float b, u32& lop) {
    bf16 h0 = __float2bfloat16(a), h1 = __float2bfloat16(b);
    bf16 l0 = __float2bfloat16(a - __bfloat162float(h0));
    bf16 l1 = __float2bfloat16(b - __bfloat162float(h1));
    __nv_bfloat162 hv, lv;
    hv.x = h0; hv.y = h1; lv.x = l0; lv.y = l1;
    lop = *(u32*)&lv;
    return *(u32*)&hv;
}

// ---------------- mean per channel + zero Gram ----------------
__global__ void mean_kernel(const float* __restrict__ X) {
    int c = blockIdx.x;
    float s = 0.f;
    for (int idx = threadIdx.x; idx < (M_TOT / 4); idx += 256) {
        int n = idx >> 8, h4 = idx & 255;
        const float4 v = *(const float4*)&X[(((size_t)(n * C_DIM + c)) << 10) + (size_t)h4 * 4];
        s += (v.x + v.y) + (v.z + v.w);
    }
    __shared__ float red[256];
    red[threadIdx.x] = s;
    __syncthreads();
    for (int off = 128; off > 0; off >>= 1) {
        if (threadIdx.x < off) red[threadIdx.x] += red[threadIdx.x + off];
        __syncthreads();
    }
    if (threadIdx.x == 0) g_mean[c] = red[0] * (1.0f / (float)M_TOT);
    for (int j = threadIdx.x; j < C_DIM; j += 256) g_Gram[(long)c * C_DIM + j] = 0.f;
}

// ---------------- center + split -> Xh/Xl [c][m] ----------------
__global__ void convA(const float* __restrict__ X) {
    int c = blockIdx.x;
    float mu = g_mean[c];
    u32* H = (u32*)&g_Xh[(long)c << 16];
    u32* L = (u32*)&g_Xl[(long)c << 16];
    for (int p = threadIdx.x; p < 32768; p += 256) {
        int m = p * 2, n = m >> 10, hw = m & 1023;
        const float2 v = *(const float2*)&X[(((long)(n * C_DIM + c)) << 10) + hw];
        u32 lo, hi = splitpack(v.x - mu, v.y - mu, lo);
        H[p] = hi; L[p] = lo;
    }
}

// ---------------- center + split + transpose -> Xth/Xtl [m][c] ----------------
__global__ void convB(const float* __restrict__ X) {
    __shared__ float smf[64][129];
    int b = blockIdx.x;
    int n = b >> 3, hw0 = (b & 7) << 7;
    int tid = threadIdx.x;
    for (int cb = 0; cb < 8; cb++) {
        __syncthreads();
        for (int l = tid; l < 64 * 32; l += 256) {
            int cl = l >> 5, f4 = (l & 31) * 4;
            int ch = cb * 64 + cl;
            float4 v = *(const float4*)&X[(((long)(n * C_DIM + ch)) << 10) + hw0 + f4];
            float mu = g_mean[ch];
            smf[cl][f4] = v.x - mu; smf[cl][f4 + 1] = v.y - mu;
            smf[cl][f4 + 2] = v.z - mu; smf[cl][f4 + 3] = v.w - mu;
        }
        __syncthreads();
        for (int l = tid; l < 128 * 32; l += 256) {
            int r = l >> 5, j = l & 31;
            u32 lo, hi = splitpack(smf[2 * j][r], smf[2 * j + 1][r], lo);
            long m = (long)n * 1024 + hw0 + r;
            ((u32*)&g_Xth[m * C_DIM])[cb * 32 + j] = hi;
            ((u32*)&g_Xtl[m * C_DIM])[cb * 32 + j] = lo;
        }
    }
}

// ---------------- big bf16x3 HMMA GEMM: 128x128 tiles, BK=64, pipelined ----------------
// mode 0: atomicAdd f32 (gram) ; mode 1: NCHW output write
__global__ void __launch_bounds__(256, 1) gemm_hmma(
    const bf16* __restrict__ Ah, const bf16* __restrict__ Al, int lda,
    const bf16* __restrict__ Bh, const bf16* __restrict__ Bl, int ldb,
    int kSlice, int mode, int tri, float* __restrict__ outF)
{
    extern __shared__ char sm_raw[];
    u32 sbase = s2u(sm_raw);
    int tid = threadIdx.x, lane = tid & 31, wid = tid >> 5;
    int wm = wid >> 1, wn = wid & 1;
    int bi, bj;
    if (tri) { bi = c_bi[blockIdx.x]; bj = c_bj[blockIdx.x]; }
    else { bi = blockIdx.y; bj = blockIdx.x; }
    const int row0 = bi * 128, col0 = bj * 128;
    const long k0 = (long)blockIdx.z * kSlice;
    const int nSteps = kSlice >> 6;

    float c[2][8][4];
#pragma unroll
    for (int mi = 0; mi < 2; mi++)
#pragma unroll
        for (int f = 0; f < 8; f++)
#pragma unroll
            for (int q = 0; q < 4; q++) c[mi][f][q] = 0.f;

    u32 ah[2][2][4], al[2][2][4], bh[2][4][4], bl[2][4][4];

    auto load_stage = [&](int st, int ks) {
        u32 sb = sbase + st * STAGE_B;
        long kg = k0 + ((long)ks << 6);
#pragma unroll
        for (int t = 0; t < 4; t++) {
            const bf16* g = (t == 0) ? Ah : (t == 1) ? Al : (t == 2) ? Bh : Bl;
            long rbase = (t < 2) ? row0 : col0;
            long ld = (t < 2) ? lda : ldb;
#pragma unroll
            for (int rep = 0; rep < 4; rep++) {
                int idx = tid + rep * 256;
                int r = idx >> 3, ch = idx & 7;
                cpasync16(sb + t * TILE_B + r * ROWB + ch * 16,
                          g + (rbase + r) * ld + kg + ch * 8);
            }
        }
        asm volatile("cp.async.commit_group;");
    };
    auto load_frags = [&](int fb, u32 sb, int kk) {
        int kcol = kk * 16;
#pragma unroll
        for (int mi = 0; mi < 2; mi++) {
            int r = wm * 32 + mi * 16 + (lane & 15);
            int cb = (kcol + (lane >> 4) * 8) * 2;
            ldm4(ah[fb][mi], sb + 0 * TILE_B + r * ROWB + cb);
            ldm4(al[fb][mi], sb + 1 * TILE_B + r * ROWB + cb);
        }
#pragma unroll
        for (int nj = 0; nj < 4; nj++) {
            int r = wn * 64 + nj * 16 + (lane & 7) + ((lane >> 4) << 3);
            int cb = (kcol + ((lane >> 3) & 1) * 8) * 2;
            ldm4(bh[fb][nj], sb + 2 * TILE_B + r * ROWB + cb);
            ldm4(bl[fb][nj], sb + 3 * TILE_B + r * ROWB + cb);
        }
    };
    auto mma_all = [&](int fb) {
#pragma unroll
        for (int mi = 0; mi < 2; mi++)
#pragma unroll
            for (int nj = 0; nj < 4; nj++) {
                mma16816(c[mi][nj * 2],     ah[fb][mi], bh[fb][nj][0], bh[fb][nj][1]);
                mma16816(c[mi][nj * 2 + 1], ah[fb][mi], bh[fb][nj][2], bh[fb][nj][3]);
                mma16816(c[mi][nj * 2],     ah[fb][mi], bl[fb][nj][0], bl[fb][nj][1]);
                mma16816(c[mi][nj * 2 + 1], ah[fb][mi], bl[fb][nj][2], bl[fb][nj][3]);
                mma16816(c[mi][nj * 2],     al[fb][mi], bh[fb][nj][0], bh[fb][nj][1]);
                mma16816(c[mi][nj * 2 + 1], al[fb][mi], bh[fb][nj][2], bh[fb][nj][3]);
            }
    };

    load_stage(0, 0);
    if (nSteps > 1) {
        load_stage(1, 1);
        asm volatile("cp.async.wait_group 1;" ::: "memory");
    } else {
        asm volatile("cp.async.wait_group 0;" ::: "memory");
    }
    __syncthreads();
    load_frags(0, sbase, 0);

    for (int ks = 0; ks < nSteps; ks++) {
        u32 sb = sbase + (ks & 1) * STAGE_B;
#pragma unroll
        for (int kk = 0; kk < 4; kk++) {
            if (kk < 3) load_frags((kk + 1) & 1, sb, kk + 1);
            mma_all(kk & 1);
        }
        if (ks + 1 < nSteps) {
            __syncthreads();
            if (ks + 2 < nSteps) {
                load_stage(ks & 1, ks + 2);
                asm volatile("cp.async.wait_group 1;" ::: "memory");
            } else {
                asm volatile("cp.async.wait_group 0;" ::: "memory");
            }
            __syncthreads();
            load_frags(0, sbase + ((ks + 1) & 1) * STAGE_B, 0);
        }
    }

    int rg = lane >> 2, cg = (lane & 3) * 2;
    if (mode == 0) {
#pragma unroll
        for (int mi = 0; mi < 2; mi++)
#pragma unroll
            for (int f = 0; f < 8; f++) {
                int rr = row0 + wm * 32 + mi * 16 + rg;
                int cc = col0 + wn * 64 + f * 8 + cg;
                atomicAdd(&outF[(long)rr * C_DIM + cc],           c[mi][f][0]);
                atomicAdd(&outF[(long)rr * C_DIM + cc + 1],       c[mi][f][1]);
                atomicAdd(&outF[(long)(rr + 8) * C_DIM + cc],     c[mi][f][2]);
                atomicAdd(&outF[(long)(rr + 8) * C_DIM + cc + 1], c[mi][f][3]);
            }
    } else {
        __syncthreads();
        float* st = (float*)sm_raw;
        const int LDS = 132;
#pragma unroll
        for (int mi = 0; mi < 2; mi++)
#pragma unroll
            for (int f = 0; f < 8; f++) {
                int rr = wm * 32 + mi * 16 + rg;
                int cc = wn * 64 + f * 8 + cg;
                st[rr * LDS + cc] = c[mi][f][0];
                st[rr * LDS + cc + 1] = c[mi][f][1];
                st[(rr + 8) * LDS + cc] = c[mi][f][2];
                st[(rr + 8) * LDS + cc + 1] = c[mi][f][3];
            }
        __syncthreads();
        int n = col0 >> 10, hw0 = col0 & 1023;
        for (int l = tid; l < 128 * 32; l += 256) {
            int r = l >> 5, q = l & 31;
            float4 v = *(float4*)&st[r * LDS + q * 4];
            *(float4*)&outF[(((long)(n * C_DIM + row0 + r)) << 10) + hw0 + q * 4] = v;
        }
    }
}

// ---------------- small bf16x3 HMMA GEMM: 64x64 tiles, K=512, fused NS epilogues ----------------
// mode 2: write split bf16 (h/l) ; mode 3: v = 1.5*Pf - 0.5*acc -> Pfn f32 + split(v*scale)
__global__ void __launch_bounds__(128, 1) gemm64(
    const bf16* __restrict__ Ah, const bf16* __restrict__ Al,
    const bf16* __restrict__ Bh, const bf16* __restrict__ Bl,
    int mode, const float* __restrict__ Pf, float* __restrict__ Pfn,
    bf16* __restrict__ outH, bf16* __restrict__ outL, int scaleFlag)
{
    extern __shared__ char sm_raw[];
    u32 sbase = s2u(sm_raw);
    int tid = threadIdx.x, lane = tid & 31, wid = tid >> 5;
    int wm = wid >> 1, wn = wid & 1;
    const int row0 = blockIdx.y * 64, col0 = blockIdx.x * 64;
    const int nSteps = 8;     // K = 512, BK = 64

    float c[2][4][4];
#pragma unroll
    for (int mi = 0; mi < 2; mi++)
#pragma unroll
        for (int f = 0; f < 4; f++)
#pragma unroll
            for (int q = 0; q < 4; q++) c[mi][f][q] = 0.f;

    u32 ah[2][2][4], al[2][2][4], bh[2][2][4], bl[2][2][4];

    auto load_stage = [&](int st, int ks) {
        u32 sb = sbase + st * STAGE64;
        long kg = (long)ks << 6;
#pragma unroll
        for (int t = 0; t < 4; t++) {
            const bf16* g = (t == 0) ? Ah : (t == 1) ? Al : (t == 2) ? Bh : Bl;
            long rbase = (t < 2) ? row0 : col0;
#pragma unroll
            for (int rep = 0; rep < 4; rep++) {
                int idx = tid + rep * 128;
                int r = idx >> 3, ch = idx & 7;
                cpasync16(sb + t * TILE64 + r * ROWB + ch * 16,
                          g + (rbase + r) * C_DIM + kg + ch * 8);
            }
        }
        asm volatile("cp.async.commit_group;");
    };
    auto load_frags = [&](int fb, u32 sb, int kk) {
        int kcol = kk * 16;
#pragma unroll
        for (int mi = 0; mi < 2; mi++) {
            int r = wm * 32 + mi * 16 + (lane & 15);
            int cb = (kcol + (lane >> 4) * 8) * 2;
            ldm4(ah[fb][mi], sb + 0 * TILE64 + r * ROWB + cb);
            ldm4(al[fb][mi], sb + 1 * TILE64 + r * ROWB + cb);
        }
#pragma unroll
        for (int nj = 0; nj < 2; nj++) {
            int r = wn * 32 + nj * 16 + (lane & 7) + ((lane >> 4) << 3);
            int cb = (kcol + ((lane >> 3) & 1) * 8) * 2;
            ldm4(bh[fb][nj], sb + 2 * TILE64 + r * ROWB + cb);
            ldm4(bl[fb][nj], sb + 3 * TILE64 + r * ROWB + cb);
        }
    };
    auto mma_all = [&](int fb) {
#pragma unroll
        for (int mi = 0; mi < 2; mi++)
#pragma unroll
            for (int nj = 0; nj < 2; nj++) {
                mma16816(c[mi][nj * 2],     ah[fb][mi], bh[fb][nj][0], bh[fb][nj][1]);
                mma16816(c[mi][nj * 2 + 1], ah[fb][mi], bh[fb][nj][2], bh[fb][nj][3]);
                mma16816(c[mi][nj * 2],     ah[fb][mi], bl[fb][nj][0], bl[fb][nj][1]);
                mma16816(c[mi][nj * 2 + 1], ah[fb][mi], bl[fb][nj][2], bl[fb][nj][3]);
                mma16816(c[mi][nj * 2],     al[fb][mi], bh[fb][nj][0], bh[fb][nj][1]);
                mma16816(c[mi][nj * 2 + 1], al[fb][mi], bh[fb][nj][2], bh[fb][nj][3]);
            }
    };

    load_stage(0, 0);
    load_stage(1, 1);
    asm volatile("cp.async.wait_group 1;" ::: "memory");
    __syncthreads();
    load_frags(0, sbase, 0);

    for (int ks = 0; ks < nSteps; ks++) {
        u32 sb = sbase + (ks & 1) * STAGE64;
#pragma unroll
        for (int kk = 0; kk < 4; kk++) {
            if (kk < 3) load_frags((kk + 1) & 1, sb, kk + 1);
            mma_all(kk & 1);
        }
        if (ks + 1 < nSteps) {
            __syncthreads();
            if (ks + 2 < nSteps) {
                load_stage(ks & 1, ks + 2);
                asm volatile("cp.async.wait_group 1;" ::: "memory");
            } else {
                asm volatile("cp.async.wait_group 0;" ::: "memory");
            }
            __syncthreads();
            load_frags(0, sbase + ((ks + 1) & 1) * STAGE64, 0);
        }
    }

    int rg = lane >> 2, cg = (lane & 3) * 2;
    float sc = (mode == 3 && scaleFlag) ? sqrtf(g_rTr) : 1.f;
#pragma unroll
    for (int mi = 0; mi < 2; mi++)
#pragma unroll
        for (int f = 0; f < 4; f++) {
            int rr = row0 + wm * 32 + mi * 16 + rg;
            int cc = col0 + wn * 32 + (f >> 1) * 16 + (f & 1) * 8 + cg;
#pragma unroll
            for (int half = 0; half < 2; half++) {
                int r2 = rr + half * 8;
                float v0 = c[mi][f][half * 2], v1 = c[mi][f][half * 2 + 1];
                long fi = (long)r2 * C_DIM + cc;
                if (mode == 3) {
                    v0 = fmaf(-0.5f, v0, 1.5f * Pf[fi]);
                    v1 = fmaf(-0.5f, v1, 1.5f * Pf[fi + 1]);
                    Pfn[fi] = v0; Pfn[fi + 1] = v1;
                    v0 *= sc; v1 *= sc;
                }
                u32 lo, hi = splitpack(v0, v1, lo);
                ((u32*)outH)[fi >> 1] = hi;
                ((u32*)outL)[fi >> 1] = lo;
            }
        }
}

// ---------------- trace -> rTr ----------------
__global__ void trace_k() {
    __shared__ float red[256];
    float s = 0.f;
    for (int i = threadIdx.x; i < C_DIM; i += 256) s += g_Gram[(long)i * (C_DIM + 1)];
    red[threadIdx.x] = s;
    __syncthreads();
    for (int off = 128; off > 0; off >>= 1) {
        if (threadIdx.x < off) red[threadIdx.x] += red[threadIdx.x + off];
        __syncthreads();
    }
    if (threadIdx.x == 0)
        g_rTr = 1.0f / (red[0] * (1.0f / (float)M_TOT) + (float)C_DIM * EPS_V);
}

// ---------------- Sigma_N split (mirrored read) + P1 = 1.5I - 0.5 Sigma_N ----------------
__global__ void finalize_k() {
    int i = blockIdx.x;
    int j2 = threadIdx.x;
    int j = j2 * 2;
    float rtr = g_rTr;
    int bi = i >> 7;
    float r0 = (bi <= (j >> 7)) ? g_Gram[(long)i * C_DIM + j] : g_Gram[(long)j * C_DIM + i];
    float r1 = (bi <= ((j + 1) >> 7)) ? g_Gram[(long)i * C_DIM + j + 1] : g_Gram[(long)(j + 1) * C_DIM + i];
    float s0 = r0 * (1.f / (float)M_TOT);
    float s1 = r1 * (1.f / (float)M_TOT);
    if (i == j) s0 += EPS_V;
    if (i == j + 1) s1 += EPS_V;
    s0 *= rtr; s1 *= rtr;
    u32 lo, hi = splitpack(s0, s1, lo);
    ((u32*)g_Sh)[i * 256 + j2] = hi; ((u32*)g_Sl)[i * 256 + j2] = lo;
    float p0 = ((i == j) ? 1.5f : 0.f) - 0.5f * s0;
    float p1 = ((i == j + 1) ? 1.5f : 0.f) - 0.5f * s1;
    g_PfA[(long)i * C_DIM + j] = p0;
    g_PfA[(long)i * C_DIM + j + 1] = p1;
    hi = splitpack(p0, p1, lo);
    ((u32*)g_PAh)[i * 256 + j2] = hi; ((u32*)g_PAl)[i * 256 + j2] = lo;
}

// ---------------- launch ----------------
extern "C" void kernel_launch(void* const* d_in, const int* in_sizes, int n_in,
                              void* d_out, int out_size) {
    const float* X = (const float*)d_in[0];
    float* Out = (float*)d_out;

    cudaFuncSetAttribute(gemm_hmma, cudaFuncAttributeMaxDynamicSharedMemorySize, GSMEM);
    cudaFuncSetAttribute(gemm64, cudaFuncAttributeMaxDynamicSharedMemorySize, GSMEM64);

    void *xh, *xl, *xth, *xtl, *sh, *sl, *pah, *pal, *pbh, *pbl;
    void *t1h, *t1l, *t2h, *t2l, *wh, *wl, *pfa, *pfb, *gram;
    cudaGetSymbolAddress(&xh, g_Xh);   cudaGetSymbolAddress(&xl, g_Xl);
    cudaGetSymbolAddress(&xth, g_Xth); cudaGetSymbolAddress(&xtl, g_Xtl);
    cudaGetSymbolAddress(&sh, g_Sh);   cudaGetSymbolAddress(&sl, g_Sl);
    cudaGetSymbolAddress(&pah, g_PAh); cudaGetSymbolAddress(&pal, g_PAl);
    cudaGetSymbolAddress(&pbh, g_PBh); cudaGetSymbolAddress(&pbl, g_PBl);
    cudaGetSymbolAddress(&t1h, g_T1h); cudaGetSymbolAddress(&t1l, g_T1l);
    cudaGetSymbolAddress(&t2h, g_T2h); cudaGetSymbolAddress(&t2l, g_T2l);
    cudaGetSymbolAddress(&wh, g_Wh);   cudaGetSymbolAddress(&wl, g_Wl);
    cudaGetSymbolAddress(&pfa, g_PfA); cudaGetSymbolAddress(&pfb, g_PfB);
    cudaGetSymbolAddress(&gram, g_Gram);

    mean_kernel<<<C_DIM, 256>>>(X);
    convA<<<C_DIM, 256>>>(X);
    convB<<<512, 256>>>(X);

    // Gram upper block-triangle only (10 tiles), K split 8 ways, atomic f32
    gemm_hmma<<<dim3(10, 1, 8), 256, GSMEM>>>(
        (const bf16*)xh, (const bf16*)xl, M_TOT,
        (const bf16*)xh, (const bf16*)xl, M_TOT, 8192, 0, 1, (float*)gram);

    trace_k<<<1, 256>>>();
    finalize_k<<<C_DIM, 256>>>();

    // Newton-Schulz iterations 2..5 (iter 1 folded into finalize_k), fused epilogues
    float *pfc = (float*)pfa, *pfn = (float*)pfb;
    bf16 *pch = (bf16*)pah, *pcl = (bf16*)pal, *pnh = (bf16*)pbh, *pnl = (bf16*)pbl;
    for (int it = 0; it < 4; it++) {
        int last = (it == 3);
        gemm64<<<dim3(8, 8), 128, GSMEM64>>>(
            pch, pcl, pch, pcl, 2, nullptr, nullptr, (bf16*)t1h, (bf16*)t1l, 0);
        gemm64<<<dim3(8, 8), 128, GSMEM64>>>(
            (const bf16*)t1h, (const bf16*)t1l, pch, pcl, 2,
            nullptr, nullptr, (bf16*)t2h, (bf16*)t2l, 0);
        gemm64<<<dim3(8, 8), 128, GSMEM64>>>(
            (const bf16*)t2h, (const bf16*)t2l, (const bf16*)sh, (const bf16*)sl, 3,
            pfc, pfn, last ? (bf16*)wh : pnh, last ? (bf16*)wl : pnl, last);
        float* tf = pfc; pfc = pfn; pfn = tf;
        bf16* th = pch; pch = pnh; pnh = th;
        bf16* tl = pcl; pcl = pnl; pnl = tl;
    }

    // Out[c][m] = W @ xc, written NCHW
    gemm_hmma<<<dim3(512, 4, 1), 256, GSMEM>>>(
        (const bf16*)wh, (const bf16*)wl, C_DIM,
        (const bf16*)xth, (const bf16*)xtl, C_DIM, 512, 1, 0, Out);
}

// round 7
// speedup vs baseline: 2.8697x; 1.2931x over previous
#include <cuda_runtime.h>
#include <cuda_bf16.h>
#include <stdint.h>
#include <math.h>

typedef __nv_bfloat16 bf16;
typedef unsigned int u32;

#define C_DIM 512
#define M_TOT 65536
#define EPS_V 1e-5f

// big GEMM tiling: CTA 128x128, BK=64, 8 warps (4x2), warp 32x64
#define ROWB 144                 // 64 bf16 = 128B data + 16B pad
#define TILE_B (128 * ROWB)      // 18432
#define STAGE_B (4 * TILE_B)     // 73728 (Ah, Al, Bh, Bl)
#define GSMEM (2 * STAGE_B)      // 147456

// small GEMM tiling: CTA 64x64, BK=64, 4 warps (2x2), warp 32x32
#define TILE64 (64 * ROWB)       // 9216
#define STAGE64 (4 * TILE64)     // 36864
#define GSMEM64 (2 * STAGE64)    // 73728

__constant__ int c_bi[10] = {0,0,0,0,1,1,1,2,2,3};
__constant__ int c_bj[10] = {0,1,2,3,1,2,3,2,3,3};

// ---------------- scratch ----------------
__device__ float g_mean[C_DIM];
__device__ float g_Gram[C_DIM * C_DIM];
__device__ float g_rTr;
__device__ bf16 g_Xh[33554432];   // centered X, [c][m]
__device__ bf16 g_Xl[33554432];
__device__ bf16 g_Xth[33554432];  // centered X, [m][c]
__device__ bf16 g_Xtl[33554432];
__device__ bf16 g_Sh[C_DIM * C_DIM], g_Sl[C_DIM * C_DIM];
__device__ bf16 g_PAh[C_DIM * C_DIM], g_PAl[C_DIM * C_DIM];
__device__ bf16 g_PBh[C_DIM * C_DIM], g_PBl[C_DIM * C_DIM];
__device__ bf16 g_T1h[C_DIM * C_DIM], g_T1l[C_DIM * C_DIM];   // P^2
__device__ bf16 g_Uh[C_DIM * C_DIM], g_Ul[C_DIM * C_DIM];     // P*Sigma
__device__ bf16 g_Wh[C_DIM * C_DIM], g_Wl[C_DIM * C_DIM];
__device__ float g_PfA[C_DIM * C_DIM], g_PfB[C_DIM * C_DIM];

// ---------------- helpers ----------------
__device__ __forceinline__ u32 s2u(const void* p) {
    u32 a;
    asm("{ .reg .u64 t; cvta.to.shared.u64 t, %1; cvt.u32.u64 %0, t; }" : "=r"(a) : "l"(p));
    return a;
}
__device__ __forceinline__ void cpasync16(u32 dst, const void* src) {
    asm volatile("cp.async.cg.shared.global [%0], [%1], 16;" :: "r"(dst), "l"(src));
}
__device__ __forceinline__ void ldm4(u32* r, u32 addr) {
    asm volatile("ldmatrix.sync.aligned.m8n8.x4.shared.b16 {%0,%1,%2,%3}, [%4];"
                 : "=r"(r[0]), "=r"(r[1]), "=r"(r[2]), "=r"(r[3]) : "r"(addr));
}
__device__ __forceinline__ void mma16816(float* c, const u32* a, u32 b0, u32 b1) {
    asm volatile("mma.sync.aligned.m16n8k16.row.col.f32.bf16.bf16.f32 "
                 "{%0,%1,%2,%3}, {%4,%5,%6,%7}, {%8,%9}, {%0,%1,%2,%3};"
                 : "+f"(c[0]), "+f"(c[1]), "+f"(c[2]), "+f"(c[3])
                 : "r"(a[0]), "r"(a[1]), "r"(a[2]), "r"(a[3]), "r"(b0), "r"(b1));
}
__device__ __forceinline__ u32 splitpack(float a, float b, u32& lop) {
    bf16 h0 = __float2bfloat16(a), h1 = __float2bfloat16(b);
    bf16 l0 = __float2bfloat16(a - __bfloat162float(h0));
    bf16 l1 = __float2bfloat16(b - __bfloat162float(h1));
    __nv_bfloat162 hv, lv;
    hv.x = h0; hv.y = h1; lv.x = l0; lv.y = l1;
    lop = *(u32*)&lv;
    return *(u32*)&hv;
}

// ---------------- mean per channel + zero Gram ----------------
__global__ void mean_kernel(const float* __restrict__ X) {
    int c = blockIdx.x;
    float s = 0.f;
    for (int idx = threadIdx.x; idx < (M_TOT / 4); idx += 256) {
        int n = idx >> 8, h4 = idx & 255;
        const float4 v = *(const float4*)&X[(((size_t)(n * C_DIM + c)) << 10) + (size_t)h4 * 4];
        s += (v.x + v.y) + (v.z + v.w);
    }
    __shared__ float red[256];
    red[threadIdx.x] = s;
    __syncthreads();
    for (int off = 128; off > 0; off >>= 1) {
        if (threadIdx.x < off) red[threadIdx.x] += red[threadIdx.x + off];
        __syncthreads();
    }
    if (threadIdx.x == 0) g_mean[c] = red[0] * (1.0f / (float)M_TOT);
    for (int j = threadIdx.x; j < C_DIM; j += 256) g_Gram[(long)c * C_DIM + j] = 0.f;
}

// ---------------- fused center+split: X -> [c][m] AND [m][c] layouts ----------------
__global__ void conv_fused(const float* __restrict__ X) {
    __shared__ float smf[64][129];
    int b = blockIdx.x;                  // 512: (n, 128-wide hw block)
    int n = b >> 3, hw0 = (b & 7) << 7;
    int tid = threadIdx.x;
    for (int cb = 0; cb < 8; cb++) {
        __syncthreads();
        for (int l = tid; l < 64 * 32; l += 256) {
            int cl = l >> 5, f4 = (l & 31) * 4;
            int ch = cb * 64 + cl;
            float4 v = *(const float4*)&X[(((long)(n * C_DIM + ch)) << 10) + hw0 + f4];
            float mu = g_mean[ch];
            smf[cl][f4] = v.x - mu; smf[cl][f4 + 1] = v.y - mu;
            smf[cl][f4 + 2] = v.z - mu; smf[cl][f4 + 3] = v.w - mu;
        }
        __syncthreads();
        // transposed [m][c] layout
        for (int l = tid; l < 128 * 32; l += 256) {
            int r = l >> 5, j = l & 31;
            u32 lo, hi = splitpack(smf[2 * j][r], smf[2 * j + 1][r], lo);
            long m = (long)n * 1024 + hw0 + r;
            ((u32*)&g_Xth[m * C_DIM])[cb * 32 + j] = hi;
            ((u32*)&g_Xtl[m * C_DIM])[cb * 32 + j] = lo;
        }
        // direct [c][m] layout
        for (int l = tid; l < 64 * 64; l += 256) {
            int cl = l >> 6, p = l & 63;
            u32 lo, hi = splitpack(smf[cl][2 * p], smf[cl][2 * p + 1], lo);
            long c = cb * 64 + cl;
            long u = (c << 15) + ((n * 1024 + hw0) >> 1) + p;
            ((u32*)g_Xh)[u] = hi;
            ((u32*)g_Xl)[u] = lo;
        }
    }
}

// ---------------- big bf16x3 HMMA GEMM: 128x128 tiles, BK=64, pipelined ----------------
// mode 0: atomicAdd f32 (gram) ; mode 1: NCHW output write
// tri: 10 upper block-triangle tiles + uneven 14-way K split (1024 steps: 74,74,73*12)
__global__ void __launch_bounds__(256, 1) gemm_hmma(
    const bf16* __restrict__ Ah, const bf16* __restrict__ Al, int lda,
    const bf16* __restrict__ Bh, const bf16* __restrict__ Bl, int ldb,
    int kSlice, int mode, int tri, float* __restrict__ outF)
{
    extern __shared__ char sm_raw[];
    u32 sbase = s2u(sm_raw);
    int tid = threadIdx.x, lane = tid & 31, wid = tid >> 5;
    int wm = wid >> 1, wn = wid & 1;
    int bi, bj, nSteps;
    long k0;
    if (tri) {
        bi = c_bi[blockIdx.x]; bj = c_bj[blockIdx.x];
        int z = blockIdx.z;
        int s0 = z * 73 + (z < 2 ? z : 2);
        nSteps = 73 + (z < 2 ? 1 : 0);
        k0 = (long)s0 << 6;
    } else {
        bi = blockIdx.y; bj = blockIdx.x;
        nSteps = kSlice >> 6;
        k0 = (long)blockIdx.z * kSlice;
    }
    const int row0 = bi * 128, col0 = bj * 128;

    float c[2][8][4];
#pragma unroll
    for (int mi = 0; mi < 2; mi++)
#pragma unroll
        for (int f = 0; f < 8; f++)
#pragma unroll
            for (int q = 0; q < 4; q++) c[mi][f][q] = 0.f;

    u32 ah[2][2][4], al[2][2][4], bh[2][4][4], bl[2][4][4];

    auto load_stage = [&](int st, int ks) {
        u32 sb = sbase + st * STAGE_B;
        long kg = k0 + ((long)ks << 6);
#pragma unroll
        for (int t = 0; t < 4; t++) {
            const bf16* g = (t == 0) ? Ah : (t == 1) ? Al : (t == 2) ? Bh : Bl;
            long rbase = (t < 2) ? row0 : col0;
            long ld = (t < 2) ? lda : ldb;
#pragma unroll
            for (int rep = 0; rep < 4; rep++) {
                int idx = tid + rep * 256;
                int r = idx >> 3, ch = idx & 7;
                cpasync16(sb + t * TILE_B + r * ROWB + ch * 16,
                          g + (rbase + r) * ld + kg + ch * 8);
            }
        }
        asm volatile("cp.async.commit_group;");
    };
    auto load_frags = [&](int fb, u32 sb, int kk) {
        int kcol = kk * 16;
#pragma unroll
        for (int mi = 0; mi < 2; mi++) {
            int r = wm * 32 + mi * 16 + (lane & 15);
            int cb = (kcol + (lane >> 4) * 8) * 2;
            ldm4(ah[fb][mi], sb + 0 * TILE_B + r * ROWB + cb);
            ldm4(al[fb][mi], sb + 1 * TILE_B + r * ROWB + cb);
        }
#pragma unroll
        for (int nj = 0; nj < 4; nj++) {
            int r = wn * 64 + nj * 16 + (lane & 7) + ((lane >> 4) << 3);
            int cb = (kcol + ((lane >> 3) & 1) * 8) * 2;
            ldm4(bh[fb][nj], sb + 2 * TILE_B + r * ROWB + cb);
            ldm4(bl[fb][nj], sb + 3 * TILE_B + r * ROWB + cb);
        }
    };
    auto mma_all = [&](int fb) {
#pragma unroll
        for (int mi = 0; mi < 2; mi++)
#pragma unroll
            for (int nj = 0; nj < 4; nj++) {
                mma16816(c[mi][nj * 2],     ah[fb][mi], bh[fb][nj][0], bh[fb][nj][1]);
                mma16816(c[mi][nj * 2 + 1], ah[fb][mi], bh[fb][nj][2], bh[fb][nj][3]);
                mma16816(c[mi][nj * 2],     ah[fb][mi], bl[fb][nj][0], bl[fb][nj][1]);
                mma16816(c[mi][nj * 2 + 1], ah[fb][mi], bl[fb][nj][2], bl[fb][nj][3]);
                mma16816(c[mi][nj * 2],     al[fb][mi], bh[fb][nj][0], bh[fb][nj][1]);
                mma16816(c[mi][nj * 2 + 1], al[fb][mi], bh[fb][nj][2], bh[fb][nj][3]);
            }
    };

    load_stage(0, 0);
    if (nSteps > 1) {
        load_stage(1, 1);
        asm volatile("cp.async.wait_group 1;" ::: "memory");
    } else {
        asm volatile("cp.async.wait_group 0;" ::: "memory");
    }
    __syncthreads();
    load_frags(0, sbase, 0);

    for (int ks = 0; ks < nSteps; ks++) {
        u32 sb = sbase + (ks & 1) * STAGE_B;
#pragma unroll
        for (int kk = 0; kk < 4; kk++) {
            if (kk < 3) load_frags((kk + 1) & 1, sb, kk + 1);
            mma_all(kk & 1);
        }
        if (ks + 1 < nSteps) {
            __syncthreads();
            if (ks + 2 < nSteps) {
                load_stage(ks & 1, ks + 2);
                asm volatile("cp.async.wait_group 1;" ::: "memory");
            } else {
                asm volatile("cp.async.wait_group 0;" ::: "memory");
            }
            __syncthreads();
            load_frags(0, sbase + ((ks + 1) & 1) * STAGE_B, 0);
        }
    }

    int rg = lane >> 2, cg = (lane & 3) * 2;
    if (mode == 0) {
#pragma unroll
        for (int mi = 0; mi < 2; mi++)
#pragma unroll
            for (int f = 0; f < 8; f++) {
                int rr = row0 + wm * 32 + mi * 16 + rg;
                int cc = col0 + wn * 64 + f * 8 + cg;
                atomicAdd(&outF[(long)rr * C_DIM + cc],           c[mi][f][0]);
                atomicAdd(&outF[(long)rr * C_DIM + cc + 1],       c[mi][f][1]);
                atomicAdd(&outF[(long)(rr + 8) * C_DIM + cc],     c[mi][f][2]);
                atomicAdd(&outF[(long)(rr + 8) * C_DIM + cc + 1], c[mi][f][3]);
            }
    } else {
        __syncthreads();
        float* st = (float*)sm_raw;
        const int LDS = 132;
#pragma unroll
        for (int mi = 0; mi < 2; mi++)
#pragma unroll
            for (int f = 0; f < 8; f++) {
                int rr = wm * 32 + mi * 16 + rg;
                int cc = wn * 64 + f * 8 + cg;
                st[rr * LDS + cc] = c[mi][f][0];
                st[rr * LDS + cc + 1] = c[mi][f][1];
                st[(rr + 8) * LDS + cc] = c[mi][f][2];
                st[(rr + 8) * LDS + cc + 1] = c[mi][f][3];
            }
        __syncthreads();
        int n = col0 >> 10, hw0 = col0 & 1023;
        for (int l = tid; l < 128 * 32; l += 256) {
            int r = l >> 5, q = l & 31;
            float4 v = *(float4*)&st[r * LDS + q * 4];
            *(float4*)&outF[(((long)(n * C_DIM + row0 + r)) << 10) + hw0 + q * 4] = v;
        }
    }
}

// ---------------- small bf16x3 HMMA GEMM core (64x64 tile, K=512) ----------------
template<int MODE>   // 2: split write ; 3: NS combine
__device__ __forceinline__ void gemm64_body(
    const bf16* Ah, const bf16* Al, const bf16* Bh, const bf16* Bl,
    const float* Pf, float* Pfn, bf16* outH, bf16* outL, int scaleFlag)
{
    extern __shared__ char sm_raw[];
    u32 sbase = s2u(sm_raw);
    int tid = threadIdx.x, lane = tid & 31, wid = tid >> 5;
    int wm = wid >> 1, wn = wid & 1;
    const int row0 = blockIdx.y * 64, col0 = blockIdx.x * 64;
    const int nSteps = 8;

    float c[2][4][4];
#pragma unroll
    for (int mi = 0; mi < 2; mi++)
#pragma unroll
        for (int f = 0; f < 4; f++)
#pragma unroll
            for (int q = 0; q < 4; q++) c[mi][f][q] = 0.f;

    u32 ah[2][2][4], al[2][2][4], bh[2][2][4], bl[2][2][4];

    auto load_stage = [&](int st, int ks) {
        u32 sb = sbase + st * STAGE64;
        long kg = (long)ks << 6;
#pragma unroll
        for (int t = 0; t < 4; t++) {
            const bf16* g = (t == 0) ? Ah : (t == 1) ? Al : (t == 2) ? Bh : Bl;
            long rbase = (t < 2) ? row0 : col0;
#pragma unroll
            for (int rep = 0; rep < 4; rep++) {
                int idx = tid + rep * 128;
                int r = idx >> 3, ch = idx & 7;
                cpasync16(sb + t * TILE64 + r * ROWB + ch * 16,
                          g + (rbase + r) * C_DIM + kg + ch * 8);
            }
        }
        asm volatile("cp.async.commit_group;");
    };
    auto load_frags = [&](int fb, u32 sb, int kk) {
        int kcol = kk * 16;
#pragma unroll
        for (int mi = 0; mi < 2; mi++) {
            int r = wm * 32 + mi * 16 + (lane & 15);
            int cb = (kcol + (lane >> 4) * 8) * 2;
            ldm4(ah[fb][mi], sb + 0 * TILE64 + r * ROWB + cb);
            ldm4(al[fb][mi], sb + 1 * TILE64 + r * ROWB + cb);
        }
#pragma unroll
        for (int nj = 0; nj < 2; nj++) {
            int r = wn * 32 + nj * 16 + (lane & 7) + ((lane >> 4) << 3);
            int cb = (kcol + ((lane >> 3) & 1) * 8) * 2;
            ldm4(bh[fb][nj], sb + 2 * TILE64 + r * ROWB + cb);
            ldm4(bl[fb][nj], sb + 3 * TILE64 + r * ROWB + cb);
        }
    };
    auto mma_all = [&](int fb) {
#pragma unroll
        for (int mi = 0; mi < 2; mi++)
#pragma unroll
            for (int nj = 0; nj < 2; nj++) {
                mma16816(c[mi][nj * 2],     ah[fb][mi], bh[fb][nj][0], bh[fb][nj][1]);
                mma16816(c[mi][nj * 2 + 1], ah[fb][mi], bh[fb][nj][2], bh[fb][nj][3]);
                mma16816(c[mi][nj * 2],     ah[fb][mi], bl[fb][nj][0], bl[fb][nj][1]);
                mma16816(c[mi][nj * 2 + 1], ah[fb][mi], bl[fb][nj][2], bl[fb][nj][3]);
                mma16816(c[mi][nj * 2],     al[fb][mi], bh[fb][nj][0], bh[fb][nj][1]);
                mma16816(c[mi][nj * 2 + 1], al[fb][mi], bh[fb][nj][2], bh[fb][nj][3]);
            }
    };

    load_stage(0, 0);
    load_stage(1, 1);
    asm volatile("cp.async.wait_group 1;" ::: "memory");
    __syncthreads();
    load_frags(0, sbase, 0);

    for (int ks = 0; ks < nSteps; ks++) {
        u32 sb = sbase + (ks & 1) * STAGE64;
#pragma unroll
        for (int kk = 0; kk < 4; kk++) {
            if (kk < 3) load_frags((kk + 1) & 1, sb, kk + 1);
            mma_all(kk & 1);
        }
        if (ks + 1 < nSteps) {
            __syncthreads();
            if (ks + 2 < nSteps) {
                load_stage(ks & 1, ks + 2);
                asm volatile("cp.async.wait_group 1;" ::: "memory");
            } else {
                asm volatile("cp.async.wait_group 0;" ::: "memory");
            }
            __syncthreads();
            load_frags(0, sbase + ((ks + 1) & 1) * STAGE64, 0);
        }
    }

    int rg = lane >> 2, cg = (lane & 3) * 2;
    float sc = (MODE == 3 && scaleFlag) ? sqrtf(g_rTr) : 1.f;
#pragma unroll
    for (int mi = 0; mi < 2; mi++)
#pragma unroll
        for (int f = 0; f < 4; f++) {
            int rr = row0 + wm * 32 + mi * 16 + rg;
            int cc = col0 + wn * 32 + (f >> 1) * 16 + (f & 1) * 8 + cg;
#pragma unroll
            for (int half = 0; half < 2; half++) {
                int r2 = rr + half * 8;
                float v0 = c[mi][f][half * 2], v1 = c[mi][f][half * 2 + 1];
                long fi = (long)r2 * C_DIM + cc;
                if (MODE == 3) {
                    v0 = fmaf(-0.5f, v0, 1.5f * Pf[fi]);
                    v1 = fmaf(-0.5f, v1, 1.5f * Pf[fi + 1]);
                    Pfn[fi] = v0; Pfn[fi + 1] = v1;
                    v0 *= sc; v1 *= sc;
                }
                u32 lo, hi = splitpack(v0, v1, lo);
                ((u32*)outH)[fi >> 1] = hi;
                ((u32*)outL)[fi >> 1] = lo;
            }
        }
}

// ---- NS pair: z=0 computes P^2 -> T1 ; z=1 computes P*S -> U (both split bf16) ----
__global__ void __launch_bounds__(128, 1) gemm64_pair(
    const bf16* __restrict__ Ph, const bf16* __restrict__ Pl,
    const bf16* __restrict__ Sh, const bf16* __restrict__ Sl)
{
    if (blockIdx.z == 0)
        gemm64_body<2>(Ph, Pl, Ph, Pl, nullptr, nullptr, g_T1h, g_T1l, 0);
    else
        gemm64_body<2>(Ph, Pl, Sh, Sl, nullptr, nullptr, g_Uh, g_Ul, 0);
}

// ---- NS combine: C = T1 * U^T ; next = 1.5P - 0.5C ; split (optionally * sqrt(rTr)) ----
__global__ void __launch_bounds__(128, 1) gemm64_comb(
    const float* __restrict__ Pf, float* __restrict__ Pfn,
    bf16* __restrict__ outH, bf16* __restrict__ outL, int scaleFlag)
{
    gemm64_body<3>(g_T1h, g_T1l, g_Uh, g_Ul, Pf, Pfn, outH, outL, scaleFlag);
}

// ---------------- trace -> rTr ----------------
__global__ void trace_k() {
    __shared__ float red[256];
    float s = 0.f;
    for (int i = threadIdx.x; i < C_DIM; i += 256) s += g_Gram[(long)i * (C_DIM + 1)];
    red[threadIdx.x] = s;
    __syncthreads();
    for (int off = 128; off > 0; off >>= 1) {
        if (threadIdx.x < off) red[threadIdx.x] += red[threadIdx.x + off];
        __syncthreads();
    }
    if (threadIdx.x == 0)
        g_rTr = 1.0f / (red[0] * (1.0f / (float)M_TOT) + (float)C_DIM * EPS_V);
}

// ---------------- Sigma_N split (mirrored read) + P1 = 1.5I - 0.5 Sigma_N ----------------
__global__ void finalize_k() {
    int i = blockIdx.x;
    int j2 = threadIdx.x;
    int j = j2 * 2;
    float rtr = g_rTr;
    int bi = i >> 7;
    float r0 = (bi <= (j >> 7)) ? g_Gram[(long)i * C_DIM + j] : g_Gram[(long)j * C_DIM + i];
    float r1 = (bi <= ((j + 1) >> 7)) ? g_Gram[(long)i * C_DIM + j + 1] : g_Gram[(long)(j + 1) * C_DIM + i];
    float s0 = r0 * (1.f / (float)M_TOT);
    float s1 = r1 * (1.f / (float)M_TOT);
    if (i == j) s0 += EPS_V;
    if (i == j + 1) s1 += EPS_V;
    s0 *= rtr; s1 *= rtr;
    u32 lo, hi = splitpack(s0, s1, lo);
    ((u32*)g_Sh)[i * 256 + j2] = hi; ((u32*)g_Sl)[i * 256 + j2] = lo;
    float p0 = ((i == j) ? 1.5f : 0.f) - 0.5f * s0;
    float p1 = ((i == j + 1) ? 1.5f : 0.f) - 0.5f * s1;
    g_PfA[(long)i * C_DIM + j] = p0;
    g_PfA[(long)i * C_DIM + j + 1] = p1;
    hi = splitpack(p0, p1, lo);
    ((u32*)g_PAh)[i * 256 + j2] = hi; ((u32*)g_PAl)[i * 256 + j2] = lo;
}

// ---------------- launch ----------------
extern "C" void kernel_launch(void* const* d_in, const int* in_sizes, int n_in,
                              void* d_out, int out_size) {
    const float* X = (const float*)d_in[0];
    float* Out = (float*)d_out;

    cudaFuncSetAttribute(gemm_hmma, cudaFuncAttributeMaxDynamicSharedMemorySize, GSMEM);
    cudaFuncSetAttribute(gemm64_pair, cudaFuncAttributeMaxDynamicSharedMemorySize, GSMEM64);
    cudaFuncSetAttribute(gemm64_comb, cudaFuncAttributeMaxDynamicSharedMemorySize, GSMEM64);

    void *xh, *xl, *xth, *xtl, *sh, *sl, *pah, *pal, *pbh, *pbl;
    void *wh, *wl, *pfa, *pfb, *gram;
    cudaGetSymbolAddress(&xh, g_Xh);   cudaGetSymbolAddress(&xl, g_Xl);
    cudaGetSymbolAddress(&xth, g_Xth); cudaGetSymbolAddress(&xtl, g_Xtl);
    cudaGetSymbolAddress(&sh, g_Sh);   cudaGetSymbolAddress(&sl, g_Sl);
    cudaGetSymbolAddress(&pah, g_PAh); cudaGetSymbolAddress(&pal, g_PAl);
    cudaGetSymbolAddress(&pbh, g_PBh); cudaGetSymbolAddress(&pbl, g_PBl);
    cudaGetSymbolAddress(&wh, g_Wh);   cudaGetSymbolAddress(&wl, g_Wl);
    cudaGetSymbolAddress(&pfa, g_PfA); cudaGetSymbolAddress(&pfb, g_PfB);
    cudaGetSymbolAddress(&gram, g_Gram);

    mean_kernel<<<C_DIM, 256>>>(X);
    conv_fused<<<512, 256>>>(X);

    // Gram upper block-triangle (10 tiles) x uneven 14-way K split = 140 CTAs (1 wave)
    gemm_hmma<<<dim3(10, 1, 14), 256, GSMEM>>>(
        (const bf16*)xh, (const bf16*)xl, M_TOT,
        (const bf16*)xh, (const bf16*)xl, M_TOT, 0, 0, 1, (float*)gram);

    trace_k<<<1, 256>>>();
    finalize_k<<<C_DIM, 256>>>();

    // Newton-Schulz iterations 2..5 (iter 1 folded into finalize_k)
    float *pfc = (float*)pfa, *pfn = (float*)pfb;
    bf16 *pch = (bf16*)pah, *pcl = (bf16*)pal, *pnh = (bf16*)pbh, *pnl = (bf16*)pbl;
    for (int it = 0; it < 4; it++) {
        int last = (it == 3);
        gemm64_pair<<<dim3(8, 8, 2), 128, GSMEM64>>>(pch, pcl, (const bf16*)sh, (const bf16*)sl);
        gemm64_comb<<<dim3(8, 8), 128, GSMEM64>>>(
            pfc, pfn, last ? (bf16*)wh : pnh, last ? (bf16*)wl : pnl, last);
        float* tf = pfc; pfc = pfn; pfn = tf;
        bf16* th = pch; pch = pnh; pnh = th;
        bf16* tl = pcl; pcl = pnl; pnl = tl;
    }

    // Out[c][m] = W @ xc, written NCHW
    gemm_hmma<<<dim3(512, 4, 1), 256, GSMEM>>>(
        (const bf16*)wh, (const bf16*)wl, C_DIM,
        (const bf16*)xth, (const bf16*)xtl, C_DIM, 512, 1, 0, Out);
}

// round 8
// speedup vs baseline: 3.0339x; 1.0572x over previous
#include <cuda_runtime.h>
#include <cuda_bf16.h>
#include <stdint.h>
#include <math.h>

typedef __nv_bfloat16 bf16;
typedef unsigned int u32;

#define C_DIM 512
#define M_TOT 65536
#define EPS_V 1e-5f

// big GEMM tiling (gram): CTA 128x128, BK=64, 8 warps (4x2), warp 32x64
#define ROWB 144                 // 64 bf16 = 128B data + 16B pad
#define TILE_B (128 * ROWB)      // 18432
#define STAGE_B (4 * TILE_B)     // 73728 (Ah, Al, Bh, Bl)
#define GSMEM (2 * STAGE_B)      // 147456

// out GEMM tiling: CTA 128x256, BK=64, 8 warps (2x4), warp 64x64
#define TILE_A (128 * ROWB)      // 18432
#define TILE_BO (256 * ROWB)     // 36864
#define OFF_B (2 * TILE_A)       // 36864
#define STAGE_O (2 * TILE_A + 2 * TILE_BO)  // 110592
#define GSMEM_O (2 * STAGE_O)    // 221184

// small GEMM tiling: CTA 64x64, BK=64, 4 warps (2x2), warp 32x32
#define TILE64 (64 * ROWB)       // 9216
#define STAGE64 (4 * TILE64)     // 36864
#define GSMEM64 (2 * STAGE64)    // 73728

__constant__ int c_bi[10] = {0,0,0,0,1,1,1,2,2,3};
__constant__ int c_bj[10] = {0,1,2,3,1,2,3,2,3,3};

// ---------------- scratch ----------------
__device__ float g_mean[C_DIM];
__device__ float g_Gram[C_DIM * C_DIM];
__device__ float g_rTr;
__device__ bf16 g_Xh[33554432];   // centered X, [c][m]
__device__ bf16 g_Xl[33554432];
__device__ bf16 g_Xth[33554432];  // centered X, [m][c]
__device__ bf16 g_Xtl[33554432];
__device__ bf16 g_Sh[C_DIM * C_DIM], g_Sl[C_DIM * C_DIM];
__device__ bf16 g_PAh[C_DIM * C_DIM], g_PAl[C_DIM * C_DIM];
__device__ bf16 g_PBh[C_DIM * C_DIM], g_PBl[C_DIM * C_DIM];
__device__ bf16 g_T1h[C_DIM * C_DIM], g_T1l[C_DIM * C_DIM];   // P^2
__device__ bf16 g_Uh[C_DIM * C_DIM], g_Ul[C_DIM * C_DIM];     // P*Sigma
__device__ bf16 g_Wh[C_DIM * C_DIM], g_Wl[C_DIM * C_DIM];
__device__ float g_PfA[C_DIM * C_DIM], g_PfB[C_DIM * C_DIM];

// ---------------- helpers ----------------
__device__ __forceinline__ u32 s2u(const void* p) {
    u32 a;
    asm("{ .reg .u64 t; cvta.to.shared.u64 t, %1; cvt.u32.u64 %0, t; }" : "=r"(a) : "l"(p));
    return a;
}
__device__ __forceinline__ void cpasync16(u32 dst, const void* src) {
    asm volatile("cp.async.cg.shared.global [%0], [%1], 16;" :: "r"(dst), "l"(src));
}
__device__ __forceinline__ void ldm4(u32* r, u32 addr) {
    asm volatile("ldmatrix.sync.aligned.m8n8.x4.shared.b16 {%0,%1,%2,%3}, [%4];"
                 : "=r"(r[0]), "=r"(r[1]), "=r"(r[2]), "=r"(r[3]) : "r"(addr));
}
__device__ __forceinline__ void mma16816(float* c, const u32* a, u32 b0, u32 b1) {
    asm volatile("mma.sync.aligned.m16n8k16.row.col.f32.bf16.bf16.f32 "
                 "{%0,%1,%2,%3}, {%4,%5,%6,%7}, {%8,%9}, {%0,%1,%2,%3};"
                 : "+f"(c[0]), "+f"(c[1]), "+f"(c[2]), "+f"(c[3])
                 : "r"(a[0]), "r"(a[1]), "r"(a[2]), "r"(a[3]), "r"(b0), "r"(b1));
}
__device__ __forceinline__ u32 splitpack(float a, float b, u32& lop) {
    bf16 h0 = __float2bfloat16(a), h1 = __float2bfloat16(b);
    bf16 l0 = __float2bfloat16(a - __bfloat162float(h0));
    bf16 l1 = __float2bfloat16(b - __bfloat162float(h1));
    __nv_bfloat162 hv, lv;
    hv.x = h0; hv.y = h1; lv.x = l0; lv.y = l1;
    lop = *(u32*)&lv;
    return *(u32*)&hv;
}

// ---------------- mean per channel + zero Gram ----------------
__global__ void mean_kernel(const float* __restrict__ X) {
    int c = blockIdx.x;
    float s = 0.f;
    for (int idx = threadIdx.x; idx < (M_TOT / 4); idx += 256) {
        int n = idx >> 8, h4 = idx & 255;
        const float4 v = *(const float4*)&X[(((size_t)(n * C_DIM + c)) << 10) + (size_t)h4 * 4];
        s += (v.x + v.y) + (v.z + v.w);
    }
    __shared__ float red[256];
    red[threadIdx.x] = s;
    __syncthreads();
    for (int off = 128; off > 0; off >>= 1) {
        if (threadIdx.x < off) red[threadIdx.x] += red[threadIdx.x + off];
        __syncthreads();
    }
    if (threadIdx.x == 0) g_mean[c] = red[0] * (1.0f / (float)M_TOT);
    for (int j = threadIdx.x; j < C_DIM; j += 256) g_Gram[(long)c * C_DIM + j] = 0.f;
}

// ---------------- fused center+split: X -> [c][m] AND [m][c] layouts ----------------
__global__ void conv_fused(const float* __restrict__ X) {
    __shared__ float smf[64][129];
    int b = blockIdx.x;
    int n = b >> 3, hw0 = (b & 7) << 7;
    int tid = threadIdx.x;
    for (int cb = 0; cb < 8; cb++) {
        __syncthreads();
        for (int l = tid; l < 64 * 32; l += 256) {
            int cl = l >> 5, f4 = (l & 31) * 4;
            int ch = cb * 64 + cl;
            float4 v = *(const float4*)&X[(((long)(n * C_DIM + ch)) << 10) + hw0 + f4];
            float mu = g_mean[ch];
            smf[cl][f4] = v.x - mu; smf[cl][f4 + 1] = v.y - mu;
            smf[cl][f4 + 2] = v.z - mu; smf[cl][f4 + 3] = v.w - mu;
        }
        __syncthreads();
        for (int l = tid; l < 128 * 32; l += 256) {
            int r = l >> 5, j = l & 31;
            u32 lo, hi = splitpack(smf[2 * j][r], smf[2 * j + 1][r], lo);
            long m = (long)n * 1024 + hw0 + r;
            ((u32*)&g_Xth[m * C_DIM])[cb * 32 + j] = hi;
            ((u32*)&g_Xtl[m * C_DIM])[cb * 32 + j] = lo;
        }
        for (int l = tid; l < 64 * 64; l += 256) {
            int cl = l >> 6, p = l & 63;
            u32 lo, hi = splitpack(smf[cl][2 * p], smf[cl][2 * p + 1], lo);
            long c = cb * 64 + cl;
            long u = (c << 15) + ((n * 1024 + hw0) >> 1) + p;
            ((u32*)g_Xh)[u] = hi;
            ((u32*)g_Xl)[u] = lo;
        }
    }
}

// ---------------- gram bf16x3 HMMA GEMM: 128x128 tiles, tri + 14-way K split ----------------
__global__ void __launch_bounds__(256, 1) gemm_hmma(
    const bf16* __restrict__ Ah, const bf16* __restrict__ Al, int lda,
    const bf16* __restrict__ Bh, const bf16* __restrict__ Bl, int ldb,
    float* __restrict__ outF)
{
    extern __shared__ char sm_raw[];
    u32 sbase = s2u(sm_raw);
    int tid = threadIdx.x, lane = tid & 31, wid = tid >> 5;
    int wm = wid >> 1, wn = wid & 1;
    int bi = c_bi[blockIdx.x], bj = c_bj[blockIdx.x];
    int z = blockIdx.z;
    int s0 = z * 73 + (z < 2 ? z : 2);
    int nSteps = 73 + (z < 2 ? 1 : 0);
    long k0 = (long)s0 << 6;
    const int row0 = bi * 128, col0 = bj * 128;

    float c[2][8][4];
#pragma unroll
    for (int mi = 0; mi < 2; mi++)
#pragma unroll
        for (int f = 0; f < 8; f++)
#pragma unroll
            for (int q = 0; q < 4; q++) c[mi][f][q] = 0.f;

    u32 ah[2][2][4], al[2][2][4], bh[2][4][4], bl[2][4][4];

    auto load_stage = [&](int st, int ks) {
        u32 sb = sbase + st * STAGE_B;
        long kg = k0 + ((long)ks << 6);
#pragma unroll
        for (int t = 0; t < 4; t++) {
            const bf16* g = (t == 0) ? Ah : (t == 1) ? Al : (t == 2) ? Bh : Bl;
            long rbase = (t < 2) ? row0 : col0;
            long ld = (t < 2) ? lda : ldb;
#pragma unroll
            for (int rep = 0; rep < 4; rep++) {
                int idx = tid + rep * 256;
                int r = idx >> 3, ch = idx & 7;
                cpasync16(sb + t * TILE_B + r * ROWB + ch * 16,
                          g + (rbase + r) * ld + kg + ch * 8);
            }
        }
        asm volatile("cp.async.commit_group;");
    };
    auto load_frags = [&](int fb, u32 sb, int kk) {
        int kcol = kk * 16;
#pragma unroll
        for (int mi = 0; mi < 2; mi++) {
            int r = wm * 32 + mi * 16 + (lane & 15);
            int cb = (kcol + (lane >> 4) * 8) * 2;
            ldm4(ah[fb][mi], sb + 0 * TILE_B + r * ROWB + cb);
            ldm4(al[fb][mi], sb + 1 * TILE_B + r * ROWB + cb);
        }
#pragma unroll
        for (int nj = 0; nj < 4; nj++) {
            int r = wn * 64 + nj * 16 + (lane & 7) + ((lane >> 4) << 3);
            int cb = (kcol + ((lane >> 3) & 1) * 8) * 2;
            ldm4(bh[fb][nj], sb + 2 * TILE_B + r * ROWB + cb);
            ldm4(bl[fb][nj], sb + 3 * TILE_B + r * ROWB + cb);
        }
    };
    auto mma_all = [&](int fb) {
#pragma unroll
        for (int mi = 0; mi < 2; mi++)
#pragma unroll
            for (int nj = 0; nj < 4; nj++) {
                mma16816(c[mi][nj * 2],     ah[fb][mi], bh[fb][nj][0], bh[fb][nj][1]);
                mma16816(c[mi][nj * 2 + 1], ah[fb][mi], bh[fb][nj][2], bh[fb][nj][3]);
                mma16816(c[mi][nj * 2],     ah[fb][mi], bl[fb][nj][0], bl[fb][nj][1]);
                mma16816(c[mi][nj * 2 + 1], ah[fb][mi], bl[fb][nj][2], bl[fb][nj][3]);
                mma16816(c[mi][nj * 2],     al[fb][mi], bh[fb][nj][0], bh[fb][nj][1]);
                mma16816(c[mi][nj * 2 + 1], al[fb][mi], bh[fb][nj][2], bh[fb][nj][3]);
            }
    };

    load_stage(0, 0);
    load_stage(1, 1);
    asm volatile("cp.async.wait_group 1;" ::: "memory");
    __syncthreads();
    load_frags(0, sbase, 0);

    for (int ks = 0; ks < nSteps; ks++) {
        u32 sb = sbase + (ks & 1) * STAGE_B;
#pragma unroll
        for (int kk = 0; kk < 4; kk++) {
            if (kk < 3) load_frags((kk + 1) & 1, sb, kk + 1);
            mma_all(kk & 1);
        }
        if (ks + 1 < nSteps) {
            __syncthreads();
            if (ks + 2 < nSteps) {
                load_stage(ks & 1, ks + 2);
                asm volatile("cp.async.wait_group 1;" ::: "memory");
            } else {
                asm volatile("cp.async.wait_group 0;" ::: "memory");
            }
            __syncthreads();
            load_frags(0, sbase + ((ks + 1) & 1) * STAGE_B, 0);
        }
    }

    int rg = lane >> 2, cg = (lane & 3) * 2;
#pragma unroll
    for (int mi = 0; mi < 2; mi++)
#pragma unroll
        for (int f = 0; f < 8; f++) {
            int rr = row0 + wm * 32 + mi * 16 + rg;
            int cc = col0 + wn * 64 + f * 8 + cg;
            atomicAdd(&outF[(long)rr * C_DIM + cc],           c[mi][f][0]);
            atomicAdd(&outF[(long)rr * C_DIM + cc + 1],       c[mi][f][1]);
            atomicAdd(&outF[(long)(rr + 8) * C_DIM + cc],     c[mi][f][2]);
            atomicAdd(&outF[(long)(rr + 8) * C_DIM + cc + 1], c[mi][f][3]);
        }
}

// ---------------- out GEMM: CTA 128x256, warp 64x64, bf16x3, NCHW epilogue ----------------
__global__ void __launch_bounds__(256, 1) gemm_out(
    const bf16* __restrict__ Ah, const bf16* __restrict__ Al,
    const bf16* __restrict__ Bh, const bf16* __restrict__ Bl,
    float* __restrict__ outF)
{
    extern __shared__ char sm_raw[];
    u32 sbase = s2u(sm_raw);
    int tid = threadIdx.x, lane = tid & 31, wid = tid >> 5;
    int wm = wid >> 2, wn = wid & 3;           // 2 x 4 warps, each 64x64
    const int row0 = blockIdx.y * 128;         // channel rows
    const int col0 = blockIdx.x * 256;         // m cols
    const int nSteps = 8;                      // K = 512

    float c[4][8][4];
#pragma unroll
    for (int mi = 0; mi < 4; mi++)
#pragma unroll
        for (int f = 0; f < 8; f++)
#pragma unroll
            for (int q = 0; q < 4; q++) c[mi][f][q] = 0.f;

    u32 ah[4][4], al[4][4];

    auto load_stage = [&](int st, int ks) {
        u32 sb = sbase + st * STAGE_O;
        long kg = (long)ks << 6;
#pragma unroll
        for (int t = 0; t < 2; t++) {          // Ah, Al: 128 rows
            const bf16* g = t ? Al : Ah;
#pragma unroll
            for (int rep = 0; rep < 4; rep++) {
                int idx = tid + rep * 256;
                int r = idx >> 3, ch = idx & 7;
                cpasync16(sb + t * TILE_A + r * ROWB + ch * 16,
                          g + (long)(row0 + r) * C_DIM + kg + ch * 8);
            }
        }
#pragma unroll
        for (int t = 0; t < 2; t++) {          // Bh, Bl: 256 rows
            const bf16* g = t ? Bl : Bh;
#pragma unroll
            for (int rep = 0; rep < 8; rep++) {
                int idx = tid + rep * 256;
                int r = idx >> 3, ch = idx & 7;
                cpasync16(sb + OFF_B + t * TILE_BO + r * ROWB + ch * 16,
                          g + (long)(col0 + r) * C_DIM + kg + ch * 8);
            }
        }
        asm volatile("cp.async.commit_group;");
    };

    load_stage(0, 0);
    load_stage(1, 1);
    asm volatile("cp.async.wait_group 1;" ::: "memory");
    __syncthreads();

    for (int ks = 0; ks < nSteps; ks++) {
        u32 sb = sbase + (ks & 1) * STAGE_O;
#pragma unroll
        for (int kk = 0; kk < 4; kk++) {
            int kcol = kk * 16;
            // A fragments: 64 rows (4 x 16), hi + lo
#pragma unroll
            for (int mi = 0; mi < 4; mi++) {
                int r = wm * 64 + mi * 16 + (lane & 15);
                int cb = (kcol + (lane >> 4) * 8) * 2;
                ldm4(ah[mi], sb + 0 * TILE_A + r * ROWB + cb);
                ldm4(al[mi], sb + 1 * TILE_A + r * ROWB + cb);
            }
            // B: 4 groups of 16 cols, just-in-time
#pragma unroll
            for (int bq = 0; bq < 4; bq++) {
                u32 bh4[4], bl4[4];
                int r = wn * 64 + bq * 16 + (lane & 7) + ((lane >> 4) << 3);
                int cb = (kcol + ((lane >> 3) & 1) * 8) * 2;
                ldm4(bh4, sb + OFF_B + 0 * TILE_BO + r * ROWB + cb);
                ldm4(bl4, sb + OFF_B + 1 * TILE_BO + r * ROWB + cb);
#pragma unroll
                for (int mi = 0; mi < 4; mi++) {
                    mma16816(c[mi][bq * 2],     ah[mi], bh4[0], bh4[1]);
                    mma16816(c[mi][bq * 2 + 1], ah[mi], bh4[2], bh4[3]);
                    mma16816(c[mi][bq * 2],     ah[mi], bl4[0], bl4[1]);
                    mma16816(c[mi][bq * 2 + 1], ah[mi], bl4[2], bl4[3]);
                    mma16816(c[mi][bq * 2],     al[mi], bh4[0], bh4[1]);
                    mma16816(c[mi][bq * 2 + 1], al[mi], bh4[2], bh4[3]);
                }
            }
        }
        if (ks + 1 < nSteps) {
            __syncthreads();
            if (ks + 2 < nSteps) {
                load_stage(ks & 1, ks + 2);
                asm volatile("cp.async.wait_group 1;" ::: "memory");
            } else {
                asm volatile("cp.async.wait_group 0;" ::: "memory");
            }
            __syncthreads();
        }
    }

    // epilogue: stage f32 in smem, coalesced NCHW write
    __syncthreads();
    float* st = (float*)sm_raw;
    const int LDS = 260;
    int rg = lane >> 2, cg = (lane & 3) * 2;
#pragma unroll
    for (int mi = 0; mi < 4; mi++)
#pragma unroll
        for (int f = 0; f < 8; f++) {
            int rr = wm * 64 + mi * 16 + rg;
            int cc = wn * 64 + f * 8 + cg;
            st[rr * LDS + cc] = c[mi][f][0];
            st[rr * LDS + cc + 1] = c[mi][f][1];
            st[(rr + 8) * LDS + cc] = c[mi][f][2];
            st[(rr + 8) * LDS + cc + 1] = c[mi][f][3];
        }
    __syncthreads();
    int n = col0 >> 10, hw0 = col0 & 1023;
    for (int l = tid; l < 128 * 64; l += 256) {
        int r = l >> 6, q = l & 63;
        float4 v = *(float4*)&st[r * LDS + q * 4];
        *(float4*)&outF[(((long)(n * C_DIM + row0 + r)) << 10) + hw0 + q * 4] = v;
    }
}

// ---------------- small bf16x3 HMMA GEMM core (64x64 tile, K=512) ----------------
template<int MODE>   // 2: split write ; 3: NS combine
__device__ __forceinline__ void gemm64_body(
    const bf16* Ah, const bf16* Al, const bf16* Bh, const bf16* Bl,
    const float* Pf, float* Pfn, bf16* outH, bf16* outL, int scaleFlag)
{
    extern __shared__ char sm_raw[];
    u32 sbase = s2u(sm_raw);
    int tid = threadIdx.x, lane = tid & 31, wid = tid >> 5;
    int wm = wid >> 1, wn = wid & 1;
    const int row0 = blockIdx.y * 64, col0 = blockIdx.x * 64;
    const int nSteps = 8;

    float c[2][4][4];
#pragma unroll
    for (int mi = 0; mi < 2; mi++)
#pragma unroll
        for (int f = 0; f < 4; f++)
#pragma unroll
            for (int q = 0; q < 4; q++) c[mi][f][q] = 0.f;

    u32 ah[2][2][4], al[2][2][4], bh[2][2][4], bl[2][2][4];

    auto load_stage = [&](int st, int ks) {
        u32 sb = sbase + st * STAGE64;
        long kg = (long)ks << 6;
#pragma unroll
        for (int t = 0; t < 4; t++) {
            const bf16* g = (t == 0) ? Ah : (t == 1) ? Al : (t == 2) ? Bh : Bl;
            long rbase = (t < 2) ? row0 : col0;
#pragma unroll
            for (int rep = 0; rep < 4; rep++) {
                int idx = tid + rep * 128;
                int r = idx >> 3, ch = idx & 7;
                cpasync16(sb + t * TILE64 + r * ROWB + ch * 16,
                          g + (rbase + r) * C_DIM + kg + ch * 8);
            }
        }
        asm volatile("cp.async.commit_group;");
    };
    auto load_frags = [&](int fb, u32 sb, int kk) {
        int kcol = kk * 16;
#pragma unroll
        for (int mi = 0; mi < 2; mi++) {
            int r = wm * 32 + mi * 16 + (lane & 15);
            int cb = (kcol + (lane >> 4) * 8) * 2;
            ldm4(ah[fb][mi], sb + 0 * TILE64 + r * ROWB + cb);
            ldm4(al[fb][mi], sb + 1 * TILE64 + r * ROWB + cb);
        }
#pragma unroll
        for (int nj = 0; nj < 2; nj++) {
            int r = wn * 32 + nj * 16 + (lane & 7) + ((lane >> 4) << 3);
            int cb = (kcol + ((lane >> 3) & 1) * 8) * 2;
            ldm4(bh[fb][nj], sb + 2 * TILE64 + r * ROWB + cb);
            ldm4(bl[fb][nj], sb + 3 * TILE64 + r * ROWB + cb);
        }
    };
    auto mma_all = [&](int fb) {
#pragma unroll
        for (int mi = 0; mi < 2; mi++)
#pragma unroll
            for (int nj = 0; nj < 2; nj++) {
                mma16816(c[mi][nj * 2],     ah[fb][mi], bh[fb][nj][0], bh[fb][nj][1]);
                mma16816(c[mi][nj * 2 + 1], ah[fb][mi], bh[fb][nj][2], bh[fb][nj][3]);
                mma16816(c[mi][nj * 2],     ah[fb][mi], bl[fb][nj][0], bl[fb][nj][1]);
                mma16816(c[mi][nj * 2 + 1], ah[fb][mi], bl[fb][nj][2], bl[fb][nj][3]);
                mma16816(c[mi][nj * 2],     al[fb][mi], bh[fb][nj][0], bh[fb][nj][1]);
                mma16816(c[mi][nj * 2 + 1], al[fb][mi], bh[fb][nj][2], bh[fb][nj][3]);
            }
    };

    load_stage(0, 0);
    load_stage(1, 1);
    asm volatile("cp.async.wait_group 1;" ::: "memory");
    __syncthreads();
    load_frags(0, sbase, 0);

    for (int ks = 0; ks < nSteps; ks++) {
        u32 sb = sbase + (ks & 1) * STAGE64;
#pragma unroll
        for (int kk = 0; kk < 4; kk++) {
            if (kk < 3) load_frags((kk + 1) & 1, sb, kk + 1);
            mma_all(kk & 1);
        }
        if (ks + 1 < nSteps) {
            __syncthreads();
            if (ks + 2 < nSteps) {
                load_stage(ks & 1, ks + 2);
                asm volatile("cp.async.wait_group 1;" ::: "memory");
            } else {
                asm volatile("cp.async.wait_group 0;" ::: "memory");
            }
            __syncthreads();
            load_frags(0, sbase + ((ks + 1) & 1) * STAGE64, 0);
        }
    }

    int rg = lane >> 2, cg = (lane & 3) * 2;
    float sc = (MODE == 3 && scaleFlag) ? sqrtf(g_rTr) : 1.f;
#pragma unroll
    for (int mi = 0; mi < 2; mi++)
#pragma unroll
        for (int f = 0; f < 4; f++) {
            int rr = row0 + wm * 32 + mi * 16 + rg;
            int cc = col0 + wn * 32 + (f >> 1) * 16 + (f & 1) * 8 + cg;
#pragma unroll
            for (int half = 0; half < 2; half++) {
                int r2 = rr + half * 8;
                float v0 = c[mi][f][half * 2], v1 = c[mi][f][half * 2 + 1];
                long fi = (long)r2 * C_DIM + cc;
                if (MODE == 3) {
                    v0 = fmaf(-0.5f, v0, 1.5f * Pf[fi]);
                    v1 = fmaf(-0.5f, v1, 1.5f * Pf[fi + 1]);
                    Pfn[fi] = v0; Pfn[fi + 1] = v1;
                    v0 *= sc; v1 *= sc;
                }
                u32 lo, hi = splitpack(v0, v1, lo);
                ((u32*)outH)[fi >> 1] = hi;
                ((u32*)outL)[fi >> 1] = lo;
            }
        }
}

__global__ void __launch_bounds__(128, 1) gemm64_pair(
    const bf16* __restrict__ Ph, const bf16* __restrict__ Pl,
    const bf16* __restrict__ Sh, const bf16* __restrict__ Sl)
{
    if (blockIdx.z == 0)
        gemm64_body<2>(Ph, Pl, Ph, Pl, nullptr, nullptr, g_T1h, g_T1l, 0);
    else
        gemm64_body<2>(Ph, Pl, Sh, Sl, nullptr, nullptr, g_Uh, g_Ul, 0);
}

__global__ void __launch_bounds__(128, 1) gemm64_comb(
    const float* __restrict__ Pf, float* __restrict__ Pfn,
    bf16* __restrict__ outH, bf16* __restrict__ outL, int scaleFlag)
{
    gemm64_body<3>(g_T1h, g_T1l, g_Uh, g_Ul, Pf, Pfn, outH, outL, scaleFlag);
}

// ---------------- trace -> rTr ----------------
__global__ void trace_k() {
    __shared__ float red[256];
    float s = 0.f;
    for (int i = threadIdx.x; i < C_DIM; i += 256) s += g_Gram[(long)i * (C_DIM + 1)];
    red[threadIdx.x] = s;
    __syncthreads();
    for (int off = 128; off > 0; off >>= 1) {
        if (threadIdx.x < off) red[threadIdx.x] += red[threadIdx.x + off];
        __syncthreads();
    }
    if (threadIdx.x == 0)
        g_rTr = 1.0f / (red[0] * (1.0f / (float)M_TOT) + (float)C_DIM * EPS_V);
}

// ---------------- Sigma_N split (mirrored read) + P1 = 1.5I - 0.5 Sigma_N ----------------
__global__ void finalize_k() {
    int i = blockIdx.x;
    int j2 = threadIdx.x;
    int j = j2 * 2;
    float rtr = g_rTr;
    int bi = i >> 7;
    float r0 = (bi <= (j >> 7)) ? g_Gram[(long)i * C_DIM + j] : g_Gram[(long)j * C_DIM + i];
    float r1 = (bi <= ((j + 1) >> 7)) ? g_Gram[(long)i * C_DIM + j + 1] : g_Gram[(long)(j + 1) * C_DIM + i];
    float s0 = r0 * (1.f / (float)M_TOT);
    float s1 = r1 * (1.f / (float)M_TOT);
    if (i == j) s0 += EPS_V;
    if (i == j + 1) s1 += EPS_V;
    s0 *= rtr; s1 *= rtr;
    u32 lo, hi = splitpack(s0, s1, lo);
    ((u32*)g_Sh)[i * 256 + j2] = hi; ((u32*)g_Sl)[i * 256 + j2] = lo;
    float p0 = ((i == j) ? 1.5f : 0.f) - 0.5f * s0;
    float p1 = ((i == j + 1) ? 1.5f : 0.f) - 0.5f * s1;
    g_PfA[(long)i * C_DIM + j] = p0;
    g_PfA[(long)i * C_DIM + j + 1] = p1;
    hi = splitpack(p0, p1, lo);
    ((u32*)g_PAh)[i * 256 + j2] = hi; ((u32*)g_PAl)[i * 256 + j2] = lo;
}

// ---------------- launch ----------------
extern "C" void kernel_launch(void* const* d_in, const int* in_sizes, int n_in,
                              void* d_out, int out_size) {
    const float* X = (const float*)d_in[0];
    float* Out = (float*)d_out;

    cudaFuncSetAttribute(gemm_hmma, cudaFuncAttributeMaxDynamicSharedMemorySize, GSMEM);
    cudaFuncSetAttribute(gemm_out, cudaFuncAttributeMaxDynamicSharedMemorySize, GSMEM_O);
    cudaFuncSetAttribute(gemm64_pair, cudaFuncAttributeMaxDynamicSharedMemorySize, GSMEM64);
    cudaFuncSetAttribute(gemm64_comb, cudaFuncAttributeMaxDynamicSharedMemorySize, GSMEM64);

    void *xh, *xl, *xth, *xtl, *sh, *sl, *pah, *pal, *pbh, *pbl;
    void *wh, *wl, *pfa, *pfb, *gram;
    cudaGetSymbolAddress(&xh, g_Xh);   cudaGetSymbolAddress(&xl, g_Xl);
    cudaGetSymbolAddress(&xth, g_Xth); cudaGetSymbolAddress(&xtl, g_Xtl);
    cudaGetSymbolAddress(&sh, g_Sh);   cudaGetSymbolAddress(&sl, g_Sl);
    cudaGetSymbolAddress(&pah, g_PAh); cudaGetSymbolAddress(&pal, g_PAl);
    cudaGetSymbolAddress(&pbh, g_PBh); cudaGetSymbolAddress(&pbl, g_PBl);
    cudaGetSymbolAddress(&wh, g_Wh);   cudaGetSymbolAddress(&wl, g_Wl);
    cudaGetSymbolAddress(&pfa, g_PfA); cudaGetSymbolAddress(&pfb, g_PfB);
    cudaGetSymbolAddress(&gram, g_Gram);

    mean_kernel<<<C_DIM, 256>>>(X);
    conv_fused<<<512, 256>>>(X);

    // Gram upper block-triangle (10 tiles) x uneven 14-way K split = 140 CTAs (1 wave)
    gemm_hmma<<<dim3(10, 1, 14), 256, GSMEM>>>(
        (const bf16*)xh, (const bf16*)xl, M_TOT,
        (const bf16*)xh, (const bf16*)xl, M_TOT, (float*)gram);

    trace_k<<<1, 256>>>();
    finalize_k<<<C_DIM, 256>>>();

    // Newton-Schulz iterations 2..5 (iter 1 folded into finalize_k)
    float *pfc = (float*)pfa, *pfn = (float*)pfb;
    bf16 *pch = (bf16*)pah, *pcl = (bf16*)pal, *pnh = (bf16*)pbh, *pnl = (bf16*)pbl;
    for (int it = 0; it < 4; it++) {
        int last = (it == 3);
        gemm64_pair<<<dim3(8, 8, 2), 128, GSMEM64>>>(pch, pcl, (const bf16*)sh, (const bf16*)sl);
        gemm64_comb<<<dim3(8, 8), 128, GSMEM64>>>(
            pfc, pfn, last ? (bf16*)wh : pnh, last ? (bf16*)wl : pnl, last);
        float* tf = pfc; pfc = pfn; pfn = tf;
        bf16* th = pch; pch = pnh; pnh = th;
        bf16* tl = pcl; pcl = pnl; pnl = tl;
    }

    // Out[c][m] = W @ xc, written NCHW (CTA 128x256, 1024 CTAs)
    gemm_out<<<dim3(256, 4), 256, GSMEM_O>>>(
        (const bf16*)wh, (const bf16*)wl,
        (const bf16*)xth, (const bf16*)xtl, Out);
}

// round 9
// speedup vs baseline: 3.1040x; 1.0231x over previous
#include <cuda_runtime.h>
#include <cuda_bf16.h>
#include <stdint.h>
#include <math.h>

typedef __nv_bfloat16 bf16;
typedef unsigned int u32;

#define C_DIM 512
#define M_TOT 65536
#define EPS_V 1e-5f

#define ROWB 144                 // 64 bf16 = 128B data + 16B pad
// 128x256 tiling (gram_big + gemm_out): BK=64, 8 warps (2x4), warp 64x64
#define TILE_A (128 * ROWB)      // 18432
#define TILE_BO (256 * ROWB)     // 36864
#define OFF_B (2 * TILE_A)       // 36864
#define STAGE_O (2 * TILE_A + 2 * TILE_BO)  // 110592
#define GSMEM_O (2 * STAGE_O)    // 221184

// NS tiling: CTA 64x64, 256 threads, 2 K-groups of 4 warps (2x2, warp 32x32)
#define TILE64 (64 * ROWB)       // 9216
#define STAGE64G (4 * TILE64)    // 36864 (Ah, Al, Bh, Bl)
#define NS_SMEM (4 * STAGE64G)   // 147456 = 2 groups x 2 stages

// gram tri tiling: 4 wide (128x256) + 2 narrow (128x128) tiles
__constant__ int c_tr[6] = {0, 0, 128, 256, 128, 384};
__constant__ int c_tc[6] = {0, 256, 256, 256, 128, 384};

// ---------------- scratch ----------------
__device__ float g_mean[C_DIM];
__device__ float g_Gram[C_DIM * C_DIM];
__device__ float g_rTr;
__device__ bf16 g_Xh[33554432];   // centered X, [c][m]
__device__ bf16 g_Xl[33554432];
__device__ bf16 g_Xth[33554432];  // centered X, [m][c]
__device__ bf16 g_Xtl[33554432];
__device__ bf16 g_Sh[C_DIM * C_DIM], g_Sl[C_DIM * C_DIM];
__device__ bf16 g_PAh[C_DIM * C_DIM], g_PAl[C_DIM * C_DIM];
__device__ bf16 g_PBh[C_DIM * C_DIM], g_PBl[C_DIM * C_DIM];
__device__ bf16 g_T1h[C_DIM * C_DIM], g_T1l[C_DIM * C_DIM];   // P^2
__device__ bf16 g_Uh[C_DIM * C_DIM], g_Ul[C_DIM * C_DIM];     // P*Sigma
__device__ bf16 g_Wh[C_DIM * C_DIM], g_Wl[C_DIM * C_DIM];
__device__ float g_PfA[C_DIM * C_DIM], g_PfB[C_DIM * C_DIM];

// ---------------- helpers ----------------
__device__ __forceinline__ u32 s2u(const void* p) {
    u32 a;
    asm("{ .reg .u64 t; cvta.to.shared.u64 t, %1; cvt.u32.u64 %0, t; }" : "=r"(a) : "l"(p));
    return a;
}
__device__ __forceinline__ void cpasync16(u32 dst, const void* src) {
    asm volatile("cp.async.cg.shared.global [%0], [%1], 16;" :: "r"(dst), "l"(src));
}
__device__ __forceinline__ void ldm4(u32* r, u32 addr) {
    asm volatile("ldmatrix.sync.aligned.m8n8.x4.shared.b16 {%0,%1,%2,%3}, [%4];"
                 : "=r"(r[0]), "=r"(r[1]), "=r"(r[2]), "=r"(r[3]) : "r"(addr));
}
__device__ __forceinline__ void mma16816(float* c, const u32* a, u32 b0, u32 b1) {
    asm volatile("mma.sync.aligned.m16n8k16.row.col.f32.bf16.bf16.f32 "
                 "{%0,%1,%2,%3}, {%4,%5,%6,%7}, {%8,%9}, {%0,%1,%2,%3};"
                 : "+f"(c[0]), "+f"(c[1]), "+f"(c[2]), "+f"(c[3])
                 : "r"(a[0]), "r"(a[1]), "r"(a[2]), "r"(a[3]), "r"(b0), "r"(b1));
}
__device__ __forceinline__ u32 splitpack(float a, float b, u32& lop) {
    bf16 h0 = __float2bfloat16(a), h1 = __float2bfloat16(b);
    bf16 l0 = __float2bfloat16(a - __bfloat162float(h0));
    bf16 l1 = __float2bfloat16(b - __bfloat162float(h1));
    __nv_bfloat162 hv, lv;
    hv.x = h0; hv.y = h1; lv.x = l0; lv.y = l1;
    lop = *(u32*)&lv;
    return *(u32*)&hv;
}

// ---------------- mean per channel + zero Gram ----------------
__global__ void mean_kernel(const float* __restrict__ X) {
    int c = blockIdx.x;
    float s = 0.f;
    for (int idx = threadIdx.x; idx < (M_TOT / 4); idx += 256) {
        int n = idx >> 8, h4 = idx & 255;
        const float4 v = *(const float4*)&X[(((size_t)(n * C_DIM + c)) << 10) + (size_t)h4 * 4];
        s += (v.x + v.y) + (v.z + v.w);
    }
    __shared__ float red[256];
    red[threadIdx.x] = s;
    __syncthreads();
    for (int off = 128; off > 0; off >>= 1) {
        if (threadIdx.x < off) red[threadIdx.x] += red[threadIdx.x + off];
        __syncthreads();
    }
    if (threadIdx.x == 0) g_mean[c] = red[0] * (1.0f / (float)M_TOT);
    for (int j = threadIdx.x; j < C_DIM; j += 256) g_Gram[(long)c * C_DIM + j] = 0.f;
}

// ---------------- fused center+split: X -> [c][m] AND [m][c] layouts ----------------
__global__ void conv_fused(const float* __restrict__ X) {
    __shared__ float smf[64][129];
    int b = blockIdx.x;
    int n = b >> 3, hw0 = (b & 7) << 7;
    int tid = threadIdx.x;
    for (int cb = 0; cb < 8; cb++) {
        __syncthreads();
        for (int l = tid; l < 64 * 32; l += 256) {
            int cl = l >> 5, f4 = (l & 31) * 4;
            int ch = cb * 64 + cl;
            float4 v = *(const float4*)&X[(((long)(n * C_DIM + ch)) << 10) + hw0 + f4];
            float mu = g_mean[ch];
            smf[cl][f4] = v.x - mu; smf[cl][f4 + 1] = v.y - mu;
            smf[cl][f4 + 2] = v.z - mu; smf[cl][f4 + 3] = v.w - mu;
        }
        __syncthreads();
        for (int l = tid; l < 128 * 32; l += 256) {
            int r = l >> 5, j = l & 31;
            u32 lo, hi = splitpack(smf[2 * j][r], smf[2 * j + 1][r], lo);
            long m = (long)n * 1024 + hw0 + r;
            ((u32*)&g_Xth[m * C_DIM])[cb * 32 + j] = hi;
            ((u32*)&g_Xtl[m * C_DIM])[cb * 32 + j] = lo;
        }
        for (int l = tid; l < 64 * 64; l += 256) {
            int cl = l >> 6, p = l & 63;
            u32 lo, hi = splitpack(smf[cl][2 * p], smf[cl][2 * p + 1], lo);
            long c = cb * 64 + cl;
            long u = (c << 15) + ((n * 1024 + hw0) >> 1) + p;
            ((u32*)g_Xh)[u] = hi;
            ((u32*)g_Xl)[u] = lo;
        }
    }
}

// ---------------- gram: tri tiles (4 wide 128x256 + 2 narrow 128x128), warp 64x64/64x32 ----------------
__global__ void __launch_bounds__(256, 1) gram_big(
    const bf16* __restrict__ Ah, const bf16* __restrict__ Al,
    float* __restrict__ outF)
{
    extern __shared__ char sm_raw[];
    u32 sbase = s2u(sm_raw);
    int tid = threadIdx.x, lane = tid & 31, wid = tid >> 5;
    int wm = wid >> 2, wn = wid & 3;
    int t = blockIdx.x;
    bool wide = t < 4;
    const int row0 = c_tr[t], col0 = c_tc[t];
    int z = blockIdx.z;
    int nSteps, s0;
    if (wide) { nSteps = 35 + (z < 9 ? 1 : 0); s0 = z * 35 + (z < 9 ? z : 9); }
    else {
        if (z >= 15) return;
        nSteps = 68 + (z < 4 ? 1 : 0); s0 = z * 68 + (z < 4 ? z : 4);
    }
    long k0 = (long)s0 << 6;

    float c[4][8][4];
#pragma unroll
    for (int mi = 0; mi < 4; mi++)
#pragma unroll
        for (int f = 0; f < 8; f++)
#pragma unroll
            for (int q = 0; q < 4; q++) c[mi][f][q] = 0.f;

    u32 ah[4][4], al[4][4];

    auto load_stage = [&](int st, int ks) {
        u32 sb = sbase + st * STAGE_O;
        long kg = k0 + ((long)ks << 6);
#pragma unroll
        for (int tt = 0; tt < 2; tt++) {       // A: 128 rows
            const bf16* g = tt ? Al : Ah;
#pragma unroll
            for (int rep = 0; rep < 4; rep++) {
                int idx = tid + rep * 256;
                int r = idx >> 3, ch = idx & 7;
                cpasync16(sb + tt * TILE_A + r * ROWB + ch * 16,
                          g + (long)(row0 + r) * M_TOT + kg + ch * 8);
            }
        }
        if (wide) {
#pragma unroll
            for (int tt = 0; tt < 2; tt++) {   // B: 256 rows
                const bf16* g = tt ? Al : Ah;
#pragma unroll
                for (int rep = 0; rep < 8; rep++) {
                    int idx = tid + rep * 256;
                    int r = idx >> 3, ch = idx & 7;
                    cpasync16(sb + OFF_B + tt * TILE_BO + r * ROWB + ch * 16,
                              g + (long)(col0 + r) * M_TOT + kg + ch * 8);
                }
            }
        } else {
#pragma unroll
            for (int tt = 0; tt < 2; tt++) {   // B: 128 rows
                const bf16* g = tt ? Al : Ah;
#pragma unroll
                for (int rep = 0; rep < 4; rep++) {
                    int idx = tid + rep * 256;
                    int r = idx >> 3, ch = idx & 7;
                    cpasync16(sb + OFF_B + tt * TILE_BO + r * ROWB + ch * 16,
                              g + (long)(col0 + r) * M_TOT + kg + ch * 8);
                }
            }
        }
        asm volatile("cp.async.commit_group;");
    };

    load_stage(0, 0);
    load_stage(1, 1);
    asm volatile("cp.async.wait_group 1;" ::: "memory");
    __syncthreads();

    for (int ks = 0; ks < nSteps; ks++) {
        u32 sb = sbase + (ks & 1) * STAGE_O;
#pragma unroll
        for (int kk = 0; kk < 4; kk++) {
            int kcol = kk * 16;
#pragma unroll
            for (int mi = 0; mi < 4; mi++) {
                int r = wm * 64 + mi * 16 + (lane & 15);
                int cb = (kcol + (lane >> 4) * 8) * 2;
                ldm4(ah[mi], sb + 0 * TILE_A + r * ROWB + cb);
                ldm4(al[mi], sb + 1 * TILE_A + r * ROWB + cb);
            }
            if (wide) {
#pragma unroll
                for (int bq = 0; bq < 4; bq++) {
                    u32 bh4[4], bl4[4];
                    int r = wn * 64 + bq * 16 + (lane & 7) + ((lane >> 4) << 3);
                    int cb = (kcol + ((lane >> 3) & 1) * 8) * 2;
                    ldm4(bh4, sb + OFF_B + 0 * TILE_BO + r * ROWB + cb);
                    ldm4(bl4, sb + OFF_B + 1 * TILE_BO + r * ROWB + cb);
#pragma unroll
                    for (int mi = 0; mi < 4; mi++) {
                        mma16816(c[mi][bq * 2],     ah[mi], bh4[0], bh4[1]);
                        mma16816(c[mi][bq * 2 + 1], ah[mi], bh4[2], bh4[3]);
                        mma16816(c[mi][bq * 2],     ah[mi], bl4[0], bl4[1]);
                        mma16816(c[mi][bq * 2 + 1], ah[mi], bl4[2], bl4[3]);
                        mma16816(c[mi][bq * 2],     al[mi], bh4[0], bh4[1]);
                        mma16816(c[mi][bq * 2 + 1], al[mi], bh4[2], bh4[3]);
                    }
                }
            } else {
#pragma unroll
                for (int bq = 0; bq < 2; bq++) {
                    u32 bh4[4], bl4[4];
                    int r = wn * 32 + bq * 16 + (lane & 7) + ((lane >> 4) << 3);
                    int cb = (kcol + ((lane >> 3) & 1) * 8) * 2;
                    ldm4(bh4, sb + OFF_B + 0 * TILE_BO + r * ROWB + cb);
                    ldm4(bl4, sb + OFF_B + 1 * TILE_BO + r * ROWB + cb);
#pragma unroll
                    for (int mi = 0; mi < 4; mi++) {
                        mma16816(c[mi][bq * 2],     ah[mi], bh4[0], bh4[1]);
                        mma16816(c[mi][bq * 2 + 1], ah[mi], bh4[2], bh4[3]);
                        mma16816(c[mi][bq * 2],     ah[mi], bl4[0], bl4[1]);
                        mma16816(c[mi][bq * 2 + 1], ah[mi], bl4[2], bl4[3]);
                        mma16816(c[mi][bq * 2],     al[mi], bh4[0], bh4[1]);
                        mma16816(c[mi][bq * 2 + 1], al[mi], bh4[2], bh4[3]);
                    }
                }
            }
        }
        if (ks + 1 < nSteps) {
            __syncthreads();
            if (ks + 2 < nSteps) {
                load_stage(ks & 1, ks + 2);
                asm volatile("cp.async.wait_group 1;" ::: "memory");
            } else {
                asm volatile("cp.async.wait_group 0;" ::: "memory");
            }
            __syncthreads();
        }
    }

    int rg = lane >> 2, cg = (lane & 3) * 2;
    int nf = wide ? 8 : 4;
    int wstride = wide ? 64 : 32;
#pragma unroll
    for (int mi = 0; mi < 4; mi++)
        for (int f = 0; f < nf; f++) {
            int rr = row0 + wm * 64 + mi * 16 + rg;
            int cc = col0 + wn * wstride + f * 8 + cg;
            atomicAdd(&outF[(long)rr * C_DIM + cc],           c[mi][f][0]);
            atomicAdd(&outF[(long)rr * C_DIM + cc + 1],       c[mi][f][1]);
            atomicAdd(&outF[(long)(rr + 8) * C_DIM + cc],     c[mi][f][2]);
            atomicAdd(&outF[(long)(rr + 8) * C_DIM + cc + 1], c[mi][f][3]);
        }
}

// ---------------- out GEMM: CTA 128x256, warp 64x64, bf16x3, NCHW epilogue ----------------
__global__ void __launch_bounds__(256, 1) gemm_out(
    const bf16* __restrict__ Ah, const bf16* __restrict__ Al,
    const bf16* __restrict__ Bh, const bf16* __restrict__ Bl,
    float* __restrict__ outF)
{
    extern __shared__ char sm_raw[];
    u32 sbase = s2u(sm_raw);
    int tid = threadIdx.x, lane = tid & 31, wid = tid >> 5;
    int wm = wid >> 2, wn = wid & 3;
    const int row0 = blockIdx.y * 128;
    const int col0 = blockIdx.x * 256;
    const int nSteps = 8;

    float c[4][8][4];
#pragma unroll
    for (int mi = 0; mi < 4; mi++)
#pragma unroll
        for (int f = 0; f < 8; f++)
#pragma unroll
            for (int q = 0; q < 4; q++) c[mi][f][q] = 0.f;

    u32 ah[4][4], al[4][4];

    auto load_stage = [&](int st, int ks) {
        u32 sb = sbase + st * STAGE_O;
        long kg = (long)ks << 6;
#pragma unroll
        for (int t = 0; t < 2; t++) {
            const bf16* g = t ? Al : Ah;
#pragma unroll
            for (int rep = 0; rep < 4; rep++) {
                int idx = tid + rep * 256;
                int r = idx >> 3, ch = idx & 7;
                cpasync16(sb + t * TILE_A + r * ROWB + ch * 16,
                          g + (long)(row0 + r) * C_DIM + kg + ch * 8);
            }
        }
#pragma unroll
        for (int t = 0; t < 2; t++) {
            const bf16* g = t ? Bl : Bh;
#pragma unroll
            for (int rep = 0; rep < 8; rep++) {
                int idx = tid + rep * 256;
                int r = idx >> 3, ch = idx & 7;
                cpasync16(sb + OFF_B + t * TILE_BO + r * ROWB + ch * 16,
                          g + (long)(col0 + r) * C_DIM + kg + ch * 8);
            }
        }
        asm volatile("cp.async.commit_group;");
    };

    load_stage(0, 0);
    load_stage(1, 1);
    asm volatile("cp.async.wait_group 1;" ::: "memory");
    __syncthreads();

    for (int ks = 0; ks < nSteps; ks++) {
        u32 sb = sbase + (ks & 1) * STAGE_O;
#pragma unroll
        for (int kk = 0; kk < 4; kk++) {
            int kcol = kk * 16;
#pragma unroll
            for (int mi = 0; mi < 4; mi++) {
                int r = wm * 64 + mi * 16 + (lane & 15);
                int cb = (kcol + (lane >> 4) * 8) * 2;
                ldm4(ah[mi], sb + 0 * TILE_A + r * ROWB + cb);
                ldm4(al[mi], sb + 1 * TILE_A + r * ROWB + cb);
            }
#pragma unroll
            for (int bq = 0; bq < 4; bq++) {
                u32 bh4[4], bl4[4];
                int r = wn * 64 + bq * 16 + (lane & 7) + ((lane >> 4) << 3);
                int cb = (kcol + ((lane >> 3) & 1) * 8) * 2;
                ldm4(bh4, sb + OFF_B + 0 * TILE_BO + r * ROWB + cb);
                ldm4(bl4, sb + OFF_B + 1 * TILE_BO + r * ROWB + cb);
#pragma unroll
                for (int mi = 0; mi < 4; mi++) {
                    mma16816(c[mi][bq * 2],     ah[mi], bh4[0], bh4[1]);
                    mma16816(c[mi][bq * 2 + 1], ah[mi], bh4[2], bh4[3]);
                    mma16816(c[mi][bq * 2],     ah[mi], bl4[0], bl4[1]);
                    mma16816(c[mi][bq * 2 + 1], ah[mi], bl4[2], bl4[3]);
                    mma16816(c[mi][bq * 2],     al[mi], bh4[0], bh4[1]);
                    mma16816(c[mi][bq * 2 + 1], al[mi], bh4[2], bh4[3]);
                }
            }
        }
        if (ks + 1 < nSteps) {
            __syncthreads();
            if (ks + 2 < nSteps) {
                load_stage(ks & 1, ks + 2);
                asm volatile("cp.async.wait_group 1;" ::: "memory");
            } else {
                asm volatile("cp.async.wait_group 0;" ::: "memory");
            }
            __syncthreads();
        }
    }

    __syncthreads();
    float* st = (float*)sm_raw;
    const int LDS = 260;
    int rg = lane >> 2, cg = (lane & 3) * 2;
#pragma unroll
    for (int mi = 0; mi < 4; mi++)
#pragma unroll
        for (int f = 0; f < 8; f++) {
            int rr = wm * 64 + mi * 16 + rg;
            int cc = wn * 64 + f * 8 + cg;
            st[rr * LDS + cc] = c[mi][f][0];
            st[rr * LDS + cc + 1] = c[mi][f][1];
            st[(rr + 8) * LDS + cc] = c[mi][f][2];
            st[(rr + 8) * LDS + cc + 1] = c[mi][f][3];
        }
    __syncthreads();
    int n = col0 >> 10, hw0 = col0 & 1023;
    for (int l = tid; l < 128 * 64; l += 256) {
        int r = l >> 6, q = l & 63;
        float4 v = *(float4*)&st[r * LDS + q * 4];
        *(float4*)&outF[(((long)(n * C_DIM + row0 + r)) << 10) + hw0 + q * 4] = v;
    }
}

// ---------------- NS GEMM core: 64x64 tile, 256 thr, 2 K-groups (split-K in CTA) ----------------
template<int MODE>   // 2: split write ; 3: NS combine
__device__ __forceinline__ void gemm64_body(
    const bf16* Ah, const bf16* Al, const bf16* Bh, const bf16* Bl,
    const float* Pf, float* Pfn, bf16* outH, bf16* outL, int scaleFlag)
{
    extern __shared__ char sm_raw[];
    u32 sbase = s2u(sm_raw);
    int tid = threadIdx.x, lane = tid & 31, wid = tid >> 5;
    int grp = wid >> 2, wi = wid & 3;
    int wm = wi >> 1, wn = wi & 1;
    int tg = tid & 127;
    const int row0 = blockIdx.y * 64, col0 = blockIdx.x * 64;
    u32 gbase = sbase + grp * (2 * STAGE64G);

    auto barg = [&]() {
        asm volatile("bar.sync %0, %1;" :: "r"(grp + 1), "r"(128) : "memory");
    };

    float c[2][4][4];
#pragma unroll
    for (int mi = 0; mi < 2; mi++)
#pragma unroll
        for (int f = 0; f < 4; f++)
#pragma unroll
            for (int q = 0; q < 4; q++) c[mi][f][q] = 0.f;

    u32 ah[2][2][4], al[2][2][4], bh[2][2][4], bl[2][2][4];

    auto load_stage = [&](int st, int ks) {
        u32 sb = gbase + st * STAGE64G;
        long kg = (long)grp * 256 + ((long)ks << 6);
#pragma unroll
        for (int t = 0; t < 4; t++) {
            const bf16* g = (t == 0) ? Ah : (t == 1) ? Al : (t == 2) ? Bh : Bl;
            long rbase = (t < 2) ? row0 : col0;
#pragma unroll
            for (int rep = 0; rep < 4; rep++) {
                int idx = tg + rep * 128;
                int r = idx >> 3, ch = idx & 7;
                cpasync16(sb + t * TILE64 + r * ROWB + ch * 16,
                          g + (rbase + r) * C_DIM + kg + ch * 8);
            }
        }
        asm volatile("cp.async.commit_group;");
    };
    auto load_frags = [&](int fb, u32 sb, int kk) {
        int kcol = kk * 16;
#pragma unroll
        for (int mi = 0; mi < 2; mi++) {
            int r = wm * 32 + mi * 16 + (lane & 15);
            int cb = (kcol + (lane >> 4) * 8) * 2;
            ldm4(ah[fb][mi], sb + 0 * TILE64 + r * ROWB + cb);
            ldm4(al[fb][mi], sb + 1 * TILE64 + r * ROWB + cb);
        }
#pragma unroll
        for (int nj = 0; nj < 2; nj++) {
            int r = wn * 32 + nj * 16 + (lane & 7) + ((lane >> 4) << 3);
            int cb = (kcol + ((lane >> 3) & 1) * 8) * 2;
            ldm4(bh[fb][nj], sb + 2 * TILE64 + r * ROWB + cb);
            ldm4(bl[fb][nj], sb + 3 * TILE64 + r * ROWB + cb);
        }
    };
    auto mma_all = [&](int fb) {
#pragma unroll
        for (int mi = 0; mi < 2; mi++)
#pragma unroll
            for (int nj = 0; nj < 2; nj++) {
                mma16816(c[mi][nj * 2],     ah[fb][mi], bh[fb][nj][0], bh[fb][nj][1]);
                mma16816(c[mi][nj * 2 + 1], ah[fb][mi], bh[fb][nj][2], bh[fb][nj][3]);
                mma16816(c[mi][nj * 2],     ah[fb][mi], bl[fb][nj][0], bl[fb][nj][1]);
                mma16816(c[mi][nj * 2 + 1], ah[fb][mi], bl[fb][nj][2], bl[fb][nj][3]);
                mma16816(c[mi][nj * 2],     al[fb][mi], bh[fb][nj][0], bh[fb][nj][1]);
                mma16816(c[mi][nj * 2 + 1], al[fb][mi], bh[fb][nj][2], bh[fb][nj][3]);
            }
    };

    load_stage(0, 0);
    load_stage(1, 1);
    asm volatile("cp.async.wait_group 1;" ::: "memory");
    barg();
    load_frags(0, gbase, 0);

    for (int ks = 0; ks < 4; ks++) {
        u32 sb = gbase + (ks & 1) * STAGE64G;
#pragma unroll
        for (int kk = 0; kk < 4; kk++) {
            if (kk < 3) load_frags((kk + 1) & 1, sb, kk + 1);
            mma_all(kk & 1);
        }
        if (ks + 1 < 4) {
            barg();
            if (ks + 2 < 4) {
                load_stage(ks & 1, ks + 2);
                asm volatile("cp.async.wait_group 1;" ::: "memory");
            } else {
                asm volatile("cp.async.wait_group 0;" ::: "memory");
            }
            barg();
            load_frags(0, gbase + ((ks + 1) & 1) * STAGE64G, 0);
        }
    }

    // cross-group reduction + epilogue
    float* red = (float*)sm_raw;   // 64x64 f32 = 16 KB (stage data dead)
    int rg = lane >> 2, cg = (lane & 3) * 2;
    __syncthreads();
    if (grp == 1) {
#pragma unroll
        for (int mi = 0; mi < 2; mi++)
#pragma unroll
            for (int f = 0; f < 4; f++) {
                int lrr = wm * 32 + mi * 16 + rg;
                int lcc = wn * 32 + (f >> 1) * 16 + (f & 1) * 8 + cg;
#pragma unroll
                for (int half = 0; half < 2; half++) {
                    red[(lrr + half * 8) * 64 + lcc]     = c[mi][f][half * 2];
                    red[(lrr + half * 8) * 64 + lcc + 1] = c[mi][f][half * 2 + 1];
                }
            }
    }
    __syncthreads();
    if (grp == 0) {
        float sc = (MODE == 3 && scaleFlag) ? sqrtf(g_rTr) : 1.f;
#pragma unroll
        for (int mi = 0; mi < 2; mi++)
#pragma unroll
            for (int f = 0; f < 4; f++) {
                int lrr = wm * 32 + mi * 16 + rg;
                int lcc = wn * 32 + (f >> 1) * 16 + (f & 1) * 8 + cg;
#pragma unroll
                for (int half = 0; half < 2; half++) {
                    int r2 = row0 + lrr + half * 8;
                    int cc = col0 + lcc;
                    float v0 = c[mi][f][half * 2]     + red[(lrr + half * 8) * 64 + lcc];
                    float v1 = c[mi][f][half * 2 + 1] + red[(lrr + half * 8) * 64 + lcc + 1];
                    long fi = (long)r2 * C_DIM + cc;
                    if (MODE == 3) {
                        v0 = fmaf(-0.5f, v0, 1.5f * Pf[fi]);
                        v1 = fmaf(-0.5f, v1, 1.5f * Pf[fi + 1]);
                        Pfn[fi] = v0; Pfn[fi + 1] = v1;
                        v0 *= sc; v1 *= sc;
                    }
                    u32 lo, hi = splitpack(v0, v1, lo);
                    ((u32*)outH)[fi >> 1] = hi;
                    ((u32*)outL)[fi >> 1] = lo;
                }
            }
    }
}

__global__ void __launch_bounds__(256, 1) gemm64_pair(
    const bf16* __restrict__ Ph, const bf16* __restrict__ Pl,
    const bf16* __restrict__ Sh, const bf16* __restrict__ Sl)
{
    if (blockIdx.z == 0)
        gemm64_body<2>(Ph, Pl, Ph, Pl, nullptr, nullptr, g_T1h, g_T1l, 0);
    else
        gemm64_body<2>(Ph, Pl, Sh, Sl, nullptr, nullptr, g_Uh, g_Ul, 0);
}

__global__ void __launch_bounds__(256, 1) gemm64_comb(
    const float* __restrict__ Pf, float* __restrict__ Pfn,
    bf16* __restrict__ outH, bf16* __restrict__ outL, int scaleFlag)
{
    gemm64_body<3>(g_T1h, g_T1l, g_Uh, g_Ul, Pf, Pfn, outH, outL, scaleFlag);
}

// ---------------- trace -> rTr ----------------
__global__ void trace_k() {
    __shared__ float red[256];
    float s = 0.f;
    for (int i = threadIdx.x; i < C_DIM; i += 256) s += g_Gram[(long)i * (C_DIM + 1)];
    red[threadIdx.x] = s;
    __syncthreads();
    for (int off = 128; off > 0; off >>= 1) {
        if (threadIdx.x < off) red[threadIdx.x] += red[threadIdx.x + off];
        __syncthreads();
    }
    if (threadIdx.x == 0)
        g_rTr = 1.0f / (red[0] * (1.0f / (float)M_TOT) + (float)C_DIM * EPS_V);
}

// ---------------- Sigma_N split (mirrored read) + P1 = 1.5I - 0.5 Sigma_N ----------------
__global__ void finalize_k() {
    int i = blockIdx.x;
    int j2 = threadIdx.x;
    int j = j2 * 2;
    float rtr = g_rTr;
    int bi = i >> 7;
    float r0 = (bi <= (j >> 7)) ? g_Gram[(long)i * C_DIM + j] : g_Gram[(long)j * C_DIM + i];
    float r1 = (bi <= ((j + 1) >> 7)) ? g_Gram[(long)i * C_DIM + j + 1] : g_Gram[(long)(j + 1) * C_DIM + i];
    float s0 = r0 * (1.f / (float)M_TOT);
    float s1 = r1 * (1.f / (float)M_TOT);
    if (i == j) s0 += EPS_V;
    if (i == j + 1) s1 += EPS_V;
    s0 *= rtr; s1 *= rtr;
    u32 lo, hi = splitpack(s0, s1, lo);
    ((u32*)g_Sh)[i * 256 + j2] = hi; ((u32*)g_Sl)[i * 256 + j2] = lo;
    float p0 = ((i == j) ? 1.5f : 0.f) - 0.5f * s0;
    float p1 = ((i == j + 1) ? 1.5f : 0.f) - 0.5f * s1;
    g_PfA[(long)i * C_DIM + j] = p0;
    g_PfA[(long)i * C_DIM + j + 1] = p1;
    hi = splitpack(p0, p1, lo);
    ((u32*)g_PAh)[i * 256 + j2] = hi; ((u32*)g_PAl)[i * 256 + j2] = lo;
}

// ---------------- launch ----------------
extern "C" void kernel_launch(void* const* d_in, const int* in_sizes, int n_in,
                              void* d_out, int out_size) {
    const float* X = (const float*)d_in[0];
    float* Out = (float*)d_out;

    cudaFuncSetAttribute(gram_big, cudaFuncAttributeMaxDynamicSharedMemorySize, GSMEM_O);
    cudaFuncSetAttribute(gemm_out, cudaFuncAttributeMaxDynamicSharedMemorySize, GSMEM_O);
    cudaFuncSetAttribute(gemm64_pair, cudaFuncAttributeMaxDynamicSharedMemorySize, NS_SMEM);
    cudaFuncSetAttribute(gemm64_comb, cudaFuncAttributeMaxDynamicSharedMemorySize, NS_SMEM);

    void *xh, *xl, *xth, *xtl, *sh, *sl, *pah, *pal, *pbh, *pbl;
    void *wh, *wl, *pfa, *pfb, *gram;
    cudaGetSymbolAddress(&xh, g_Xh);   cudaGetSymbolAddress(&xl, g_Xl);
    cudaGetSymbolAddress(&xth, g_Xth); cudaGetSymbolAddress(&xtl, g_Xtl);
    cudaGetSymbolAddress(&sh, g_Sh);   cudaGetSymbolAddress(&sl, g_Sl);
    cudaGetSymbolAddress(&pah, g_PAh); cudaGetSymbolAddress(&pal, g_PAl);
    cudaGetSymbolAddress(&pbh, g_PBh); cudaGetSymbolAddress(&pbl, g_PBl);
    cudaGetSymbolAddress(&wh, g_Wh);   cudaGetSymbolAddress(&wl, g_Wl);
    cudaGetSymbolAddress(&pfa, g_PfA); cudaGetSymbolAddress(&pfb, g_PfB);
    cudaGetSymbolAddress(&gram, g_Gram);

    mean_kernel<<<C_DIM, 256>>>(X);
    conv_fused<<<512, 256>>>(X);

    // Gram: 4 wide + 2 narrow tri tiles, uneven K split (wide z=29, narrow z=15)
    gram_big<<<dim3(6, 1, 29), 256, GSMEM_O>>>(
        (const bf16*)xh, (const bf16*)xl, (float*)gram);

    trace_k<<<1, 256>>>();
    finalize_k<<<C_DIM, 256>>>();

    // Newton-Schulz iterations 2..5 (iter 1 folded into finalize_k)
    float *pfc = (float*)pfa, *pfn = (float*)pfb;
    bf16 *pch = (bf16*)pah, *pcl = (bf16*)pal, *pnh = (bf16*)pbh, *pnl = (bf16*)pbl;
    for (int it = 0; it < 4; it++) {
        int last = (it == 3);
        gemm64_pair<<<dim3(8, 8, 2), 256, NS_SMEM>>>(pch, pcl, (const bf16*)sh, (const bf16*)sl);
        gemm64_comb<<<dim3(8, 8), 256, NS_SMEM>>>(
            pfc, pfn, last ? (bf16*)wh : pnh, last ? (bf16*)wl : pnl, last);
        float* tf = pfc; pfc = pfn; pfn = tf;
        bf16* th = pch; pch = pnh; pnh = th;
        bf16* tl = pcl; pcl = pnl; pnl = tl;
    }

    // Out[c][m] = W @ xc, written NCHW (CTA 128x256, 1024 CTAs)
    gemm_out<<<dim3(256, 4), 256, GSMEM_O>>>(
        (const bf16*)wh, (const bf16*)wl,
        (const bf16*)xth, (const bf16*)xtl, Out);
}